// round 8
// baseline (speedup 1.0000x reference)
#include <cuda_runtime.h>
#include <cuda_bf16.h>
#include <cstdint>

#define B_  32
#define T_  2048
#define D_  256
#define H_  256
#define G3_ 768

// Scratch (no cudaMalloc allowed): xg buffer [B,T,768] and layer-1 output [B,T,256]
__device__ float g_xg[(size_t)B_ * T_ * G3_];
__device__ float g_h1[(size_t)B_ * T_ * H_];

typedef unsigned long long u64t;

__device__ __forceinline__ unsigned smem_u32(const void* p) {
    unsigned a;
    asm("{ .reg .u64 t; cvta.to.shared.u64 t, %1; cvt.u32.u64 %0, t; }"
        : "=r"(a) : "l"(p));
    return a;
}

// ===========================================================================
// Tensor-core GEMM via baseline mma.sync (bf16, split hi/lo, 3-term).
// UNCHANGED from R7 (passing, ~0.2ms/launch).
// ===========================================================================
#define GT 256
#define KP 72
#define SM_AH 0
#define SM_AL 18432
#define SM_BH 36864
#define SM_BL 46080
#define SM_TOT 55296

__device__ __forceinline__ void mma_bf16(float& d0, float& d1, float& d2, float& d3,
                                         unsigned a0, unsigned a1, unsigned a2, unsigned a3,
                                         unsigned b0, unsigned b1) {
    asm volatile(
        "mma.sync.aligned.m16n8k16.row.col.f32.bf16.bf16.f32 "
        "{%0,%1,%2,%3}, {%4,%5,%6,%7}, {%8,%9}, {%0,%1,%2,%3};"
        : "+f"(d0), "+f"(d1), "+f"(d2), "+f"(d3)
        : "r"(a0), "r"(a1), "r"(a2), "r"(a3), "r"(b0), "r"(b1));
}

__global__ void __launch_bounds__(GT)
gemm_tc_kernel(const float* __restrict__ A, const float* __restrict__ W,
               const float* __restrict__ bias, float* __restrict__ out)
{
    extern __shared__ char smem[];
    __nv_bfloat16* Ah = (__nv_bfloat16*)(smem + SM_AH);
    __nv_bfloat16* Al = (__nv_bfloat16*)(smem + SM_AL);
    __nv_bfloat16* Bh = (__nv_bfloat16*)(smem + SM_BH);
    __nv_bfloat16* Bl = (__nv_bfloat16*)(smem + SM_BL);

    const int tid  = threadIdx.x;
    const int lane = tid & 31;
    const int w    = tid >> 5;
    const int wm   = w & 3;
    const int wn   = w >> 2;
    const int bm   = blockIdx.x * 128;
    const int bn   = blockIdx.y * 64;

    const int lr = lane >> 2;
    const int lc = (lane & 3) * 2;

    float d[2][4][4];
    #pragma unroll
    for (int mf = 0; mf < 2; mf++)
        #pragma unroll
        for (int nf = 0; nf < 4; nf++)
            #pragma unroll
            for (int e = 0; e < 4; e++) d[mf][nf][e] = 0.f;

    for (int kb = 0; kb < 4; kb++) {
        #pragma unroll
        for (int i = 0; i < 8; i++) {
            int idx = tid + i * GT;
            int row = idx >> 4;
            int c4  = (idx & 15) * 4;
            float4 v = *(const float4*)&A[(size_t)(bm + row) * 256 + kb * 64 + c4];
            __nv_bfloat162 h01 = __float22bfloat162_rn(make_float2(v.x, v.y));
            __nv_bfloat162 h23 = __float22bfloat162_rn(make_float2(v.z, v.w));
            float2 r01 = __bfloat1622float2(h01);
            float2 r23 = __bfloat1622float2(h23);
            __nv_bfloat162 l01 = __float22bfloat162_rn(make_float2(v.x - r01.x, v.y - r01.y));
            __nv_bfloat162 l23 = __float22bfloat162_rn(make_float2(v.z - r23.x, v.w - r23.y));
            *(__nv_bfloat162*)&Ah[row * KP + c4]     = h01;
            *(__nv_bfloat162*)&Ah[row * KP + c4 + 2] = h23;
            *(__nv_bfloat162*)&Al[row * KP + c4]     = l01;
            *(__nv_bfloat162*)&Al[row * KP + c4 + 2] = l23;
        }
        #pragma unroll
        for (int i = 0; i < 4; i++) {
            int idx = tid + i * GT;
            int row = idx >> 4;
            int c4  = (idx & 15) * 4;
            float4 v = *(const float4*)&W[(size_t)(bn + row) * 256 + kb * 64 + c4];
            __nv_bfloat162 h01 = __float22bfloat162_rn(make_float2(v.x, v.y));
            __nv_bfloat162 h23 = __float22bfloat162_rn(make_float2(v.z, v.w));
            float2 r01 = __bfloat1622float2(h01);
            float2 r23 = __bfloat1622float2(h23);
            __nv_bfloat162 l01 = __float22bfloat162_rn(make_float2(v.x - r01.x, v.y - r01.y));
            __nv_bfloat162 l23 = __float22bfloat162_rn(make_float2(v.z - r23.x, v.w - r23.y));
            *(__nv_bfloat162*)&Bh[row * KP + c4]     = h01;
            *(__nv_bfloat162*)&Bh[row * KP + c4 + 2] = h23;
            *(__nv_bfloat162*)&Bl[row * KP + c4]     = l01;
            *(__nv_bfloat162*)&Bl[row * KP + c4 + 2] = l23;
        }
        __syncthreads();

        #pragma unroll
        for (int k16 = 0; k16 < 4; k16++) {
            const int kk = k16 * 16;
            unsigned ah[2][4], al[2][4], bh[4][2], bl[4][2];
            #pragma unroll
            for (int mf = 0; mf < 2; mf++) {
                int r0 = wm * 32 + mf * 16 + lr;
                ah[mf][0] = *(const unsigned*)&Ah[r0 * KP + kk + lc];
                ah[mf][1] = *(const unsigned*)&Ah[(r0 + 8) * KP + kk + lc];
                ah[mf][2] = *(const unsigned*)&Ah[r0 * KP + kk + 8 + lc];
                ah[mf][3] = *(const unsigned*)&Ah[(r0 + 8) * KP + kk + 8 + lc];
                al[mf][0] = *(const unsigned*)&Al[r0 * KP + kk + lc];
                al[mf][1] = *(const unsigned*)&Al[(r0 + 8) * KP + kk + lc];
                al[mf][2] = *(const unsigned*)&Al[r0 * KP + kk + 8 + lc];
                al[mf][3] = *(const unsigned*)&Al[(r0 + 8) * KP + kk + 8 + lc];
            }
            #pragma unroll
            for (int nf = 0; nf < 4; nf++) {
                int n0 = wn * 32 + nf * 8 + lr;
                bh[nf][0] = *(const unsigned*)&Bh[n0 * KP + kk + lc];
                bh[nf][1] = *(const unsigned*)&Bh[n0 * KP + kk + 8 + lc];
                bl[nf][0] = *(const unsigned*)&Bl[n0 * KP + kk + lc];
                bl[nf][1] = *(const unsigned*)&Bl[n0 * KP + kk + 8 + lc];
            }
            #pragma unroll
            for (int mf = 0; mf < 2; mf++)
                #pragma unroll
                for (int nf = 0; nf < 4; nf++) {
                    float* dd = d[mf][nf];
                    mma_bf16(dd[0], dd[1], dd[2], dd[3],
                             ah[mf][0], ah[mf][1], ah[mf][2], ah[mf][3],
                             bh[nf][0], bh[nf][1]);
                    mma_bf16(dd[0], dd[1], dd[2], dd[3],
                             ah[mf][0], ah[mf][1], ah[mf][2], ah[mf][3],
                             bl[nf][0], bl[nf][1]);
                    mma_bf16(dd[0], dd[1], dd[2], dd[3],
                             al[mf][0], al[mf][1], al[mf][2], al[mf][3],
                             bh[nf][0], bh[nf][1]);
                }
        }
        __syncthreads();
    }

    #pragma unroll
    for (int mf = 0; mf < 2; mf++) {
        int m = bm + wm * 32 + mf * 16 + lr;
        #pragma unroll
        for (int nf = 0; nf < 4; nf++) {
            int n = bn + wn * 32 + nf * 8 + lc;
            float2 bv = *(const float2*)&bias[n];
            float2 v0 = make_float2(d[mf][nf][0] + bv.x, d[mf][nf][1] + bv.y);
            float2 v1 = make_float2(d[mf][nf][2] + bv.x, d[mf][nf][3] + bv.y);
            *(float2*)&out[(size_t)m * G3_ + n]       = v0;
            *(float2*)&out[(size_t)(m + 8) * G3_ + n] = v1;
        }
    }
}

// ===========================================================================
// Recurrent kernel: cluster of 4 CTAs per batch element (grid = 128 CTAs).
// R8 changes vs R4: (1) wait acquire scope cluster -> cta (peer release.cluster
// already performs the smem stores at cluster scope before the flip is
// observable); (2) per-warp arrives (no bar.sync 3), mbar count 8;
// (3) xg held in gate-lane registers (no xgs smem staging).
// ===========================================================================
#define RTHREADS 384
#define HPAD 272

__device__ __forceinline__ void st_cluster_f32(unsigned addr, unsigned rank, float v) {
    asm volatile(
        "{ .reg .b32 r; mapa.shared::cluster.u32 r, %0, %1; st.shared::cluster.f32 [r], %2; }"
        :: "r"(addr), "r"(rank), "f"(v) : "memory");
}
__device__ __forceinline__ void mbar_init(unsigned addr, unsigned count) {
    asm volatile("mbarrier.init.shared.b64 [%0], %1;" :: "r"(addr), "r"(count) : "memory");
}
__device__ __forceinline__ void mbar_arrive_peer(unsigned addr, unsigned rank) {
    asm volatile(
        "{ .reg .b32 r; mapa.shared::cluster.u32 r, %0, %1; "
        "mbarrier.arrive.release.cluster.shared::cluster.b64 _, [r]; }"
        :: "r"(addr), "r"(rank) : "memory");
}
__device__ __forceinline__ void mbar_wait_cta(unsigned addr, unsigned parity) {
    asm volatile(
        "{\n\t.reg .pred P1;\n\t"
        "WAIT_%=:\n\t"
        "mbarrier.try_wait.parity.acquire.cta.shared::cta.b64 P1, [%0], %1, 0x989680;\n\t"
        "@P1 bra DONE_%=;\n\t"
        "bra WAIT_%=;\n\t"
        "DONE_%=:\n\t}"
        :: "r"(addr), "r"(parity) : "memory");
}
__device__ __forceinline__ void cluster_barrier() {
    asm volatile("barrier.cluster.arrive.aligned;" ::: "memory");
    asm volatile("barrier.cluster.wait.aligned;"   ::: "memory");
}
__device__ __forceinline__ u64t ffma2(u64t a, u64t b, u64t c) {
    u64t d;
    asm("fma.rn.f32x2 %0, %1, %2, %3;" : "=l"(d) : "l"(a), "l"(b), "l"(c));
    return d;
}
__device__ __forceinline__ u64t add2(u64t a, u64t b) {
    u64t d;
    asm("add.rn.f32x2 %0, %1, %2;" : "=l"(d) : "l"(a), "l"(b));
    return d;
}
__device__ __forceinline__ float hsum2(u64t v) {
    float lo, hi;
    asm("mov.b64 {%0, %1}, %2;" : "=f"(lo), "=f"(hi) : "l"(v));
    return lo + hi;
}
__device__ __forceinline__ float fast_sigmoid(float x) {
    return 1.f / (1.f + __expf(-x));
}
__device__ __forceinline__ float fast_tanh(float x) {
    return 2.f / (1.f + __expf(-2.f * x)) - 1.f;
}

__global__ void __cluster_dims__(4, 1, 1) __launch_bounds__(RTHREADS, 1)
gru_rec_kernel(const float* __restrict__ xg, const float* __restrict__ Whh,
               const float* __restrict__ bhh, float* __restrict__ out)
{
    const int tid = threadIdx.x;
    const int s   = tid & 3;
    const int rg  = tid >> 2;
    const int b   = blockIdx.x >> 2;
    const int c   = blockIdx.x & 3;

    __shared__ __align__(16) float hb[2][HPAD];
    __shared__ float hgc[192];
    __shared__ __align__(8) unsigned long long mbar_s[2];

    u64t w2[2][32];
    #pragma unroll
    for (int q = 0; q < 2; q++) {
        int lr = rg * 2 + q;
        int g  = lr >> 6;
        int jl = lr & 63;
        const ulonglong2* wp =
            (const ulonglong2*)(Whh + (size_t)(g * 256 + c * 64 + jl) * 256 + s * 64);
        #pragma unroll
        for (int k = 0; k < 16; k++) {
            ulonglong2 v = wp[k];
            w2[q][2 * k]     = v.x;
            w2[q][2 * k + 1] = v.y;
        }
    }

    const bool gate = (tid < 64);
    const int  jglob = c * 64 + (tid & 63);
    const float* xgb = xg + (size_t)b * T_ * G3_;

    float b_r = 0.f, b_z = 0.f, b_n = 0.f;
    float xr = 0.f, xz = 0.f, xn = 0.f;
    if (gate) {
        b_r = bhh[jglob];
        b_z = bhh[256 + jglob];
        b_n = bhh[512 + jglob];
        xr = xgb[jglob];            // prefetch t=0
        xz = xgb[256 + jglob];
        xn = xgb[512 + jglob];
    }
    for (int i = tid; i < 2 * HPAD; i += RTHREADS)
        hb[0][i] = 0.f;

    const unsigned mb0 = smem_u32(&mbar_s[0]);
    const unsigned mb1 = smem_u32(&mbar_s[1]);
    if (tid == 0) { mbar_init(mb0, 8); mbar_init(mb1, 8); }   // 2 warps x 4 CTAs

    const int pidx = jglob + ((jglob >> 6) << 2);
    const unsigned addr0 = smem_u32(&hb[0][pidx]);
    const unsigned addr1 = smem_u32(&hb[1][pidx]);
    float hreg = 0.f;
    __syncthreads();
    cluster_barrier();   // mbarriers initialized before any remote arrive

    int ph0 = 0, ph1 = 0;
    int cur = 0;
    for (int t = 0; t < T_; t++) {
        if (t) {
            unsigned wa = cur ? mb1 : mb0;
            int p = cur ? ph1 : ph0;
            mbar_wait_cta(wa, p);
            if (cur) ph1 ^= 1; else ph0 ^= 1;
        }

        const ulonglong2* h2 = (const ulonglong2*)hb[cur];
        u64t a00 = 0, a01 = 0, a10 = 0, a11 = 0;
        #pragma unroll
        for (int i = 0; i < 16; i++) {
            ulonglong2 hv = h2[s * 17 + i];
            a00 = ffma2(w2[0][2 * i],     hv.x, a00);
            a01 = ffma2(w2[0][2 * i + 1], hv.y, a01);
            a10 = ffma2(w2[1][2 * i],     hv.x, a10);
            a11 = ffma2(w2[1][2 * i + 1], hv.y, a11);
        }
        float acc0 = hsum2(add2(a00, a01));
        float acc1 = hsum2(add2(a10, a11));
        acc0 += __shfl_xor_sync(0xffffffffu, acc0, 1);
        acc0 += __shfl_xor_sync(0xffffffffu, acc0, 2);
        acc1 += __shfl_xor_sync(0xffffffffu, acc1, 1);
        acc1 += __shfl_xor_sync(0xffffffffu, acc1, 2);
        if (s == 0) { hgc[rg * 2] = acc0; hgc[rg * 2 + 1] = acc1; }
        __syncthreads();

        if (gate) {
            float hr = hgc[tid]       + b_r;
            float hz = hgc[64 + tid]  + b_z;
            float hn = hgc[128 + tid] + b_n;
            float r  = fast_sigmoid(xr + hr);
            float z  = fast_sigmoid(xz + hz);
            float nn = fast_tanh(xn + r * hn);
            float hnew = (1.f - z) * nn + z * hreg;
            hreg = hnew;
            unsigned dsta = cur ? addr0 : addr1;      // write buffer cur^1
            #pragma unroll
            for (int p = 0; p < 4; p++) st_cluster_f32(dsta, p, hnew);
            __syncwarp();
            if ((tid & 31) < 4) {
                unsigned am = cur ? mb0 : mb1;        // mbar of buffer cur^1
                mbar_arrive_peer(am, (unsigned)(tid & 31));
            }
            // off critical path: output store + next-step xg prefetch
            out[((size_t)b * T_ + t) * H_ + jglob] = hnew;
            if (t + 1 < T_) {
                const float* xgt = xgb + (size_t)(t + 1) * G3_;
                xr = xgt[jglob];
                xz = xgt[256 + jglob];
                xn = xgt[512 + jglob];
            }
        }
        cur ^= 1;
    }
    cluster_barrier();   // don't exit while peers' DSMEM stores are in flight
}

// ---------------------------------------------------------------------------
static void launch_rec(const float* xg, const float* Whh, const float* bhh,
                       float* out)
{
    cudaLaunchConfig_t cfg = {};
    cfg.gridDim  = dim3(B_ * 4, 1, 1);
    cfg.blockDim = dim3(RTHREADS, 1, 1);
    cfg.dynamicSmemBytes = 0;
    cfg.stream = 0;
    cudaLaunchAttribute attrs[1];
    attrs[0].id = cudaLaunchAttributeClusterDimension;
    attrs[0].val.clusterDim.x = 4;
    attrs[0].val.clusterDim.y = 1;
    attrs[0].val.clusterDim.z = 1;
    cfg.attrs = attrs;
    cfg.numAttrs = 1;
    cudaLaunchKernelEx(&cfg, gru_rec_kernel, xg, Whh, bhh, out);
}

extern "C" void kernel_launch(void* const* d_in, const int* in_sizes, int n_in,
                              void* d_out, int out_size)
{
    (void)in_sizes; (void)n_in; (void)out_size;
    const float* x   = (const float*)d_in[0];
    const float* Wih = (const float*)d_in[1];
    const float* Whh = (const float*)d_in[2];
    const float* bih = (const float*)d_in[3];
    const float* bhh = (const float*)d_in[4];
    float* out = (float*)d_out;

    float* xgp; cudaGetSymbolAddress((void**)&xgp, g_xg);
    float* h1p; cudaGetSymbolAddress((void**)&h1p, g_h1);

    cudaFuncSetAttribute(gemm_tc_kernel,
                         cudaFuncAttributeMaxDynamicSharedMemorySize, SM_TOT);

    const dim3 ggrid(B_ * T_ / 128, G3_ / 64);

    // Layer 0
    gemm_tc_kernel<<<ggrid, GT, SM_TOT>>>(x, Wih, bih, xgp);
    launch_rec(xgp, Whh, bhh, h1p);
    // Layer 1
    gemm_tc_kernel<<<ggrid, GT, SM_TOT>>>(h1p, Wih + (size_t)G3_ * D_, bih + G3_, xgp);
    launch_rec(xgp, Whh + (size_t)G3_ * H_, bhh + G3_, out);
}

// round 9
// speedup vs baseline: 1.2103x; 1.2103x over previous
#include <cuda_runtime.h>
#include <cuda_bf16.h>
#include <cstdint>

#define B_  32
#define T_  2048
#define D_  256
#define H_  256
#define G3_ 768

// Scratch (no cudaMalloc allowed): xg buffer [B,T,768] and layer-1 output [B,T,256]
__device__ float g_xg[(size_t)B_ * T_ * G3_];
__device__ float g_h1[(size_t)B_ * T_ * H_];

typedef unsigned long long u64t;

__device__ __forceinline__ unsigned smem_u32(const void* p) {
    unsigned a;
    asm("{ .reg .u64 t; cvta.to.shared.u64 t, %1; cvt.u32.u64 %0, t; }"
        : "=r"(a) : "l"(p));
    return a;
}

// ===========================================================================
// Tensor-core GEMM via baseline mma.sync (bf16, split hi/lo, 3-term).
// UNCHANGED from R7 (passing, fast).
// ===========================================================================
#define GT 256
#define KP 72
#define SM_AH 0
#define SM_AL 18432
#define SM_BH 36864
#define SM_BL 46080
#define SM_TOT 55296

__device__ __forceinline__ void mma_bf16(float& d0, float& d1, float& d2, float& d3,
                                         unsigned a0, unsigned a1, unsigned a2, unsigned a3,
                                         unsigned b0, unsigned b1) {
    asm volatile(
        "mma.sync.aligned.m16n8k16.row.col.f32.bf16.bf16.f32 "
        "{%0,%1,%2,%3}, {%4,%5,%6,%7}, {%8,%9}, {%0,%1,%2,%3};"
        : "+f"(d0), "+f"(d1), "+f"(d2), "+f"(d3)
        : "r"(a0), "r"(a1), "r"(a2), "r"(a3), "r"(b0), "r"(b1));
}

__global__ void __launch_bounds__(GT)
gemm_tc_kernel(const float* __restrict__ A, const float* __restrict__ W,
               const float* __restrict__ bias, float* __restrict__ out)
{
    extern __shared__ char smem[];
    __nv_bfloat16* Ah = (__nv_bfloat16*)(smem + SM_AH);
    __nv_bfloat16* Al = (__nv_bfloat16*)(smem + SM_AL);
    __nv_bfloat16* Bh = (__nv_bfloat16*)(smem + SM_BH);
    __nv_bfloat16* Bl = (__nv_bfloat16*)(smem + SM_BL);

    const int tid  = threadIdx.x;
    const int lane = tid & 31;
    const int w    = tid >> 5;
    const int wm   = w & 3;
    const int wn   = w >> 2;
    const int bm   = blockIdx.x * 128;
    const int bn   = blockIdx.y * 64;

    const int lr = lane >> 2;
    const int lc = (lane & 3) * 2;

    float d[2][4][4];
    #pragma unroll
    for (int mf = 0; mf < 2; mf++)
        #pragma unroll
        for (int nf = 0; nf < 4; nf++)
            #pragma unroll
            for (int e = 0; e < 4; e++) d[mf][nf][e] = 0.f;

    for (int kb = 0; kb < 4; kb++) {
        #pragma unroll
        for (int i = 0; i < 8; i++) {
            int idx = tid + i * GT;
            int row = idx >> 4;
            int c4  = (idx & 15) * 4;
            float4 v = *(const float4*)&A[(size_t)(bm + row) * 256 + kb * 64 + c4];
            __nv_bfloat162 h01 = __float22bfloat162_rn(make_float2(v.x, v.y));
            __nv_bfloat162 h23 = __float22bfloat162_rn(make_float2(v.z, v.w));
            float2 r01 = __bfloat1622float2(h01);
            float2 r23 = __bfloat1622float2(h23);
            __nv_bfloat162 l01 = __float22bfloat162_rn(make_float2(v.x - r01.x, v.y - r01.y));
            __nv_bfloat162 l23 = __float22bfloat162_rn(make_float2(v.z - r23.x, v.w - r23.y));
            *(__nv_bfloat162*)&Ah[row * KP + c4]     = h01;
            *(__nv_bfloat162*)&Ah[row * KP + c4 + 2] = h23;
            *(__nv_bfloat162*)&Al[row * KP + c4]     = l01;
            *(__nv_bfloat162*)&Al[row * KP + c4 + 2] = l23;
        }
        #pragma unroll
        for (int i = 0; i < 4; i++) {
            int idx = tid + i * GT;
            int row = idx >> 4;
            int c4  = (idx & 15) * 4;
            float4 v = *(const float4*)&W[(size_t)(bn + row) * 256 + kb * 64 + c4];
            __nv_bfloat162 h01 = __float22bfloat162_rn(make_float2(v.x, v.y));
            __nv_bfloat162 h23 = __float22bfloat162_rn(make_float2(v.z, v.w));
            float2 r01 = __bfloat1622float2(h01);
            float2 r23 = __bfloat1622float2(h23);
            __nv_bfloat162 l01 = __float22bfloat162_rn(make_float2(v.x - r01.x, v.y - r01.y));
            __nv_bfloat162 l23 = __float22bfloat162_rn(make_float2(v.z - r23.x, v.w - r23.y));
            *(__nv_bfloat162*)&Bh[row * KP + c4]     = h01;
            *(__nv_bfloat162*)&Bh[row * KP + c4 + 2] = h23;
            *(__nv_bfloat162*)&Bl[row * KP + c4]     = l01;
            *(__nv_bfloat162*)&Bl[row * KP + c4 + 2] = l23;
        }
        __syncthreads();

        #pragma unroll
        for (int k16 = 0; k16 < 4; k16++) {
            const int kk = k16 * 16;
            unsigned ah[2][4], al[2][4], bh[4][2], bl[4][2];
            #pragma unroll
            for (int mf = 0; mf < 2; mf++) {
                int r0 = wm * 32 + mf * 16 + lr;
                ah[mf][0] = *(const unsigned*)&Ah[r0 * KP + kk + lc];
                ah[mf][1] = *(const unsigned*)&Ah[(r0 + 8) * KP + kk + lc];
                ah[mf][2] = *(const unsigned*)&Ah[r0 * KP + kk + 8 + lc];
                ah[mf][3] = *(const unsigned*)&Ah[(r0 + 8) * KP + kk + 8 + lc];
                al[mf][0] = *(const unsigned*)&Al[r0 * KP + kk + lc];
                al[mf][1] = *(const unsigned*)&Al[(r0 + 8) * KP + kk + lc];
                al[mf][2] = *(const unsigned*)&Al[r0 * KP + kk + 8 + lc];
                al[mf][3] = *(const unsigned*)&Al[(r0 + 8) * KP + kk + 8 + lc];
            }
            #pragma unroll
            for (int nf = 0; nf < 4; nf++) {
                int n0 = wn * 32 + nf * 8 + lr;
                bh[nf][0] = *(const unsigned*)&Bh[n0 * KP + kk + lc];
                bh[nf][1] = *(const unsigned*)&Bh[n0 * KP + kk + 8 + lc];
                bl[nf][0] = *(const unsigned*)&Bl[n0 * KP + kk + lc];
                bl[nf][1] = *(const unsigned*)&Bl[n0 * KP + kk + 8 + lc];
            }
            #pragma unroll
            for (int mf = 0; mf < 2; mf++)
                #pragma unroll
                for (int nf = 0; nf < 4; nf++) {
                    float* dd = d[mf][nf];
                    mma_bf16(dd[0], dd[1], dd[2], dd[3],
                             ah[mf][0], ah[mf][1], ah[mf][2], ah[mf][3],
                             bh[nf][0], bh[nf][1]);
                    mma_bf16(dd[0], dd[1], dd[2], dd[3],
                             ah[mf][0], ah[mf][1], ah[mf][2], ah[mf][3],
                             bl[nf][0], bl[nf][1]);
                    mma_bf16(dd[0], dd[1], dd[2], dd[3],
                             al[mf][0], al[mf][1], al[mf][2], al[mf][3],
                             bh[nf][0], bh[nf][1]);
                }
        }
        __syncthreads();
    }

    #pragma unroll
    for (int mf = 0; mf < 2; mf++) {
        int m = bm + wm * 32 + mf * 16 + lr;
        #pragma unroll
        for (int nf = 0; nf < 4; nf++) {
            int n = bn + wn * 32 + nf * 8 + lc;
            float2 bv = *(const float2*)&bias[n];
            float2 v0 = make_float2(d[mf][nf][0] + bv.x, d[mf][nf][1] + bv.y);
            float2 v1 = make_float2(d[mf][nf][2] + bv.x, d[mf][nf][3] + bv.y);
            *(float2*)&out[(size_t)m * G3_ + n]       = v0;
            *(float2*)&out[(size_t)(m + 8) * G3_ + n] = v1;
        }
    }
}

// ===========================================================================
// Recurrent kernel — EXACT R7/R4 structure with ONE change:
// the per-step mbarrier wait uses acquire.CTA scope instead of acquire.CLUSTER.
// (Producer's arrive.release.cluster already performs the DSMEM stores at
// cluster scope before the phase flip is observable; our reads are of our OWN
// smem, so a cta-scope acquire suffices. R8 confirmed correctness.)
// ===========================================================================
#define RTHREADS 384
#define HPAD 272

__device__ __forceinline__ void st_cluster_f32(unsigned addr, unsigned rank, float v) {
    asm volatile(
        "{ .reg .b32 r; mapa.shared::cluster.u32 r, %0, %1; st.shared::cluster.f32 [r], %2; }"
        :: "r"(addr), "r"(rank), "f"(v) : "memory");
}
__device__ __forceinline__ void mbar_init(unsigned addr, unsigned count) {
    asm volatile("mbarrier.init.shared.b64 [%0], %1;" :: "r"(addr), "r"(count) : "memory");
}
__device__ __forceinline__ void mbar_arrive_peer(unsigned addr, unsigned rank) {
    asm volatile(
        "{ .reg .b32 r; mapa.shared::cluster.u32 r, %0, %1; "
        "mbarrier.arrive.release.cluster.shared::cluster.b64 _, [r]; }"
        :: "r"(addr), "r"(rank) : "memory");
}
__device__ __forceinline__ void mbar_wait_cta(unsigned addr, unsigned parity) {
    asm volatile(
        "{\n\t.reg .pred P1;\n\t"
        "WAIT_%=:\n\t"
        "mbarrier.try_wait.parity.acquire.cta.shared::cta.b64 P1, [%0], %1, 0x989680;\n\t"
        "@P1 bra DONE_%=;\n\t"
        "bra WAIT_%=;\n\t"
        "DONE_%=:\n\t}"
        :: "r"(addr), "r"(parity) : "memory");
}
__device__ __forceinline__ void cluster_barrier() {
    asm volatile("barrier.cluster.arrive.aligned;" ::: "memory");
    asm volatile("barrier.cluster.wait.aligned;"   ::: "memory");
}
__device__ __forceinline__ u64t ffma2(u64t a, u64t b, u64t c) {
    u64t d;
    asm("fma.rn.f32x2 %0, %1, %2, %3;" : "=l"(d) : "l"(a), "l"(b), "l"(c));
    return d;
}
__device__ __forceinline__ u64t add2(u64t a, u64t b) {
    u64t d;
    asm("add.rn.f32x2 %0, %1, %2;" : "=l"(d) : "l"(a), "l"(b));
    return d;
}
__device__ __forceinline__ float hsum2(u64t v) {
    float lo, hi;
    asm("mov.b64 {%0, %1}, %2;" : "=f"(lo), "=f"(hi) : "l"(v));
    return lo + hi;
}
__device__ __forceinline__ float fast_sigmoid(float x) {
    return 1.f / (1.f + __expf(-x));
}
__device__ __forceinline__ float fast_tanh(float x) {
    return 2.f / (1.f + __expf(-2.f * x)) - 1.f;
}

__global__ void __cluster_dims__(4, 1, 1) __launch_bounds__(RTHREADS, 1)
gru_rec_kernel(const float* __restrict__ xg, const float* __restrict__ Whh,
               const float* __restrict__ bhh, float* __restrict__ out)
{
    const int tid = threadIdx.x;
    const int s   = tid & 3;
    const int rg  = tid >> 2;
    const int b   = blockIdx.x >> 2;
    const int c   = blockIdx.x & 3;

    __shared__ __align__(16) float hb[2][HPAD];
    __shared__ float hgc[192];
    __shared__ float xgs[192];
    __shared__ __align__(8) unsigned long long mbar_s[2];

    u64t w2[2][32];
    #pragma unroll
    for (int q = 0; q < 2; q++) {
        int lr = rg * 2 + q;
        int g  = lr >> 6;
        int jl = lr & 63;
        const ulonglong2* wp =
            (const ulonglong2*)(Whh + (size_t)(g * 256 + c * 64 + jl) * 256 + s * 64);
        #pragma unroll
        for (int k = 0; k < 16; k++) {
            ulonglong2 v = wp[k];
            w2[q][2 * k]     = v.x;
            w2[q][2 * k + 1] = v.y;
        }
    }

    float b_r = 0.f, b_z = 0.f, b_n = 0.f;
    if (tid < 64) {
        b_r = bhh[c * 64 + tid];
        b_z = bhh[256 + c * 64 + tid];
        b_n = bhh[512 + c * 64 + tid];
    }
    for (int i = tid; i < 2 * HPAD; i += RTHREADS)
        hb[0][i] = 0.f;

    const unsigned mb0 = smem_u32(&mbar_s[0]);
    const unsigned mb1 = smem_u32(&mbar_s[1]);
    if (tid == 0) { mbar_init(mb0, 4); mbar_init(mb1, 4); }

    const float* xgb = xg + (size_t)b * T_ * G3_;
    const int xoff = (tid >> 6) * 256 + c * 64 + (tid & 63);
    float xgc = (tid < 192) ? xgb[xoff] : 0.f;

    const int jglob = c * 64 + (tid & 63);
    const int pidx  = jglob + ((jglob >> 6) << 2);
    const unsigned addr0 = smem_u32(&hb[0][pidx]);
    const unsigned addr1 = smem_u32(&hb[1][pidx]);
    float hreg = 0.f;
    __syncthreads();
    cluster_barrier();

    int ph0 = 0, ph1 = 0;
    int cur = 0;
    for (int t = 0; t < T_; t++) {
        if (t) {
            unsigned wa = cur ? mb1 : mb0;
            int p = cur ? ph1 : ph0;
            mbar_wait_cta(wa, p);
            if (cur) ph1 ^= 1; else ph0 ^= 1;
        }
        if (tid < 192) xgs[tid] = xgc;
        float xgn = 0.f;
        if (tid < 192 && t + 1 < T_)
            xgn = xgb[(size_t)(t + 1) * G3_ + xoff];

        const ulonglong2* h2 = (const ulonglong2*)hb[cur];
        u64t a00 = 0, a01 = 0, a10 = 0, a11 = 0;
        #pragma unroll
        for (int i = 0; i < 16; i++) {
            ulonglong2 hv = h2[s * 17 + i];
            a00 = ffma2(w2[0][2 * i],     hv.x, a00);
            a01 = ffma2(w2[0][2 * i + 1], hv.y, a01);
            a10 = ffma2(w2[1][2 * i],     hv.x, a10);
            a11 = ffma2(w2[1][2 * i + 1], hv.y, a11);
        }
        float acc0 = hsum2(add2(a00, a01));
        float acc1 = hsum2(add2(a10, a11));
        acc0 += __shfl_xor_sync(0xffffffffu, acc0, 1);
        acc0 += __shfl_xor_sync(0xffffffffu, acc0, 2);
        acc1 += __shfl_xor_sync(0xffffffffu, acc1, 1);
        acc1 += __shfl_xor_sync(0xffffffffu, acc1, 2);
        if (s == 0) { hgc[rg * 2] = acc0; hgc[rg * 2 + 1] = acc1; }
        __syncthreads();

        if (tid < 64) {
            float hr = hgc[tid]       + b_r;
            float hz = hgc[64 + tid]  + b_z;
            float hn = hgc[128 + tid] + b_n;
            float xr = xgs[tid], xz = xgs[64 + tid], xn = xgs[128 + tid];
            float r  = fast_sigmoid(xr + hr);
            float z  = fast_sigmoid(xz + hz);
            float nn = fast_tanh(xn + r * hn);
            float hnew = (1.f - z) * nn + z * hreg;
            hreg = hnew;
            unsigned dsta = cur ? addr0 : addr1;
            #pragma unroll
            for (int p = 0; p < 4; p++) st_cluster_f32(dsta, p, hnew);
            out[((size_t)b * T_ + t) * H_ + jglob] = hnew;
            asm volatile("bar.sync 3, 64;" ::: "memory");
            if (tid < 4) {
                unsigned am = cur ? mb0 : mb1;
                mbar_arrive_peer(am, (unsigned)tid);
            }
        }

        xgc = xgn;
        cur ^= 1;
    }
    cluster_barrier();
}

// ---------------------------------------------------------------------------
static void launch_rec(const float* xg, const float* Whh, const float* bhh,
                       float* out)
{
    cudaLaunchConfig_t cfg = {};
    cfg.gridDim  = dim3(B_ * 4, 1, 1);
    cfg.blockDim = dim3(RTHREADS, 1, 1);
    cfg.dynamicSmemBytes = 0;
    cfg.stream = 0;
    cudaLaunchAttribute attrs[1];
    attrs[0].id = cudaLaunchAttributeClusterDimension;
    attrs[0].val.clusterDim.x = 4;
    attrs[0].val.clusterDim.y = 1;
    attrs[0].val.clusterDim.z = 1;
    cfg.attrs = attrs;
    cfg.numAttrs = 1;
    cudaLaunchKernelEx(&cfg, gru_rec_kernel, xg, Whh, bhh, out);
}

extern "C" void kernel_launch(void* const* d_in, const int* in_sizes, int n_in,
                              void* d_out, int out_size)
{
    (void)in_sizes; (void)n_in; (void)out_size;
    const float* x   = (const float*)d_in[0];
    const float* Wih = (const float*)d_in[1];
    const float* Whh = (const float*)d_in[2];
    const float* bih = (const float*)d_in[3];
    const float* bhh = (const float*)d_in[4];
    float* out = (float*)d_out;

    float* xgp; cudaGetSymbolAddress((void**)&xgp, g_xg);
    float* h1p; cudaGetSymbolAddress((void**)&h1p, g_h1);

    cudaFuncSetAttribute(gemm_tc_kernel,
                         cudaFuncAttributeMaxDynamicSharedMemorySize, SM_TOT);

    const dim3 ggrid(B_ * T_ / 128, G3_ / 64);

    // Layer 0
    gemm_tc_kernel<<<ggrid, GT, SM_TOT>>>(x, Wih, bih, xgp);
    launch_rec(xgp, Whh, bhh, h1p);
    // Layer 1
    gemm_tc_kernel<<<ggrid, GT, SM_TOT>>>(h1p, Wih + (size_t)G3_ * D_, bih + G3_, xgp);
    launch_rec(xgp, Whh + (size_t)G3_ * H_, bhh + G3_, out);
}

// round 11
// speedup vs baseline: 1.2194x; 1.0075x over previous
#include <cuda_runtime.h>
#include <cuda_bf16.h>
#include <cstdint>

#define B_  32
#define T_  2048
#define D_  256
#define H_  256
#define G3_ 768
#define CH_  256                 // chunk length (steps)
#define NCH_ (T_ / CH_)          // 8 chunks

// Scratch (no cudaMalloc allowed)
__device__ float g_xg0[(size_t)B_ * T_ * G3_];   // layer-0 input gates
__device__ float g_xg1[(size_t)B_ * T_ * G3_];   // layer-1 input gates (separate: rec0 still reads xg0)
__device__ float g_h1 [(size_t)B_ * T_ * H_];    // layer-0 output history

typedef unsigned long long u64t;

__device__ __forceinline__ unsigned smem_u32(const void* p) {
    unsigned a;
    asm("{ .reg .u64 t; cvta.to.shared.u64 t, %1; cvt.u32.u64 %0, t; }"
        : "=r"(a) : "l"(p));
    return a;
}

// ===========================================================================
// Tensor-core GEMM via baseline mma.sync (bf16, split hi/lo, 3-term).
// Same math as R7; adds (t0, bpb) so a launch can cover a T-chunk:
// block bb = blockIdx.x / bpb selects batch, chunk-local M offset inside it.
// ===========================================================================
#define GT 256
#define KP 72
#define SM_AH 0
#define SM_AL 18432
#define SM_BH 36864
#define SM_BL 46080
#define SM_TOT 55296

__device__ __forceinline__ void mma_bf16(float& d0, float& d1, float& d2, float& d3,
                                         unsigned a0, unsigned a1, unsigned a2, unsigned a3,
                                         unsigned b0, unsigned b1) {
    asm volatile(
        "mma.sync.aligned.m16n8k16.row.col.f32.bf16.bf16.f32 "
        "{%0,%1,%2,%3}, {%4,%5,%6,%7}, {%8,%9}, {%0,%1,%2,%3};"
        : "+f"(d0), "+f"(d1), "+f"(d2), "+f"(d3)
        : "r"(a0), "r"(a1), "r"(a2), "r"(a3), "r"(b0), "r"(b1));
}

__global__ void __launch_bounds__(GT)
gemm_tc_kernel(const float* __restrict__ A, const float* __restrict__ W,
               const float* __restrict__ bias, float* __restrict__ out,
               int t0, int bpb)
{
    extern __shared__ char smem[];
    __nv_bfloat16* Ah = (__nv_bfloat16*)(smem + SM_AH);
    __nv_bfloat16* Al = (__nv_bfloat16*)(smem + SM_AL);
    __nv_bfloat16* Bh = (__nv_bfloat16*)(smem + SM_BH);
    __nv_bfloat16* Bl = (__nv_bfloat16*)(smem + SM_BL);

    const int tid  = threadIdx.x;
    const int lane = tid & 31;
    const int w    = tid >> 5;
    const int wm   = w & 3;
    const int wn   = w >> 2;
    const int bb   = blockIdx.x / bpb;
    const size_t mrow0 = (size_t)bb * T_ + t0 + (size_t)(blockIdx.x % bpb) * 128;
    const int bn   = blockIdx.y * 64;

    const int lr = lane >> 2;
    const int lc = (lane & 3) * 2;

    float d[2][4][4];
    #pragma unroll
    for (int mf = 0; mf < 2; mf++)
        #pragma unroll
        for (int nf = 0; nf < 4; nf++)
            #pragma unroll
            for (int e = 0; e < 4; e++) d[mf][nf][e] = 0.f;

    for (int kb = 0; kb < 4; kb++) {
        #pragma unroll
        for (int i = 0; i < 8; i++) {
            int idx = tid + i * GT;
            int row = idx >> 4;
            int c4  = (idx & 15) * 4;
            float4 v = *(const float4*)&A[(mrow0 + row) * 256 + kb * 64 + c4];
            __nv_bfloat162 h01 = __float22bfloat162_rn(make_float2(v.x, v.y));
            __nv_bfloat162 h23 = __float22bfloat162_rn(make_float2(v.z, v.w));
            float2 r01 = __bfloat1622float2(h01);
            float2 r23 = __bfloat1622float2(h23);
            __nv_bfloat162 l01 = __float22bfloat162_rn(make_float2(v.x - r01.x, v.y - r01.y));
            __nv_bfloat162 l23 = __float22bfloat162_rn(make_float2(v.z - r23.x, v.w - r23.y));
            *(__nv_bfloat162*)&Ah[row * KP + c4]     = h01;
            *(__nv_bfloat162*)&Ah[row * KP + c4 + 2] = h23;
            *(__nv_bfloat162*)&Al[row * KP + c4]     = l01;
            *(__nv_bfloat162*)&Al[row * KP + c4 + 2] = l23;
        }
        #pragma unroll
        for (int i = 0; i < 4; i++) {
            int idx = tid + i * GT;
            int row = idx >> 4;
            int c4  = (idx & 15) * 4;
            float4 v = *(const float4*)&W[(size_t)(bn + row) * 256 + kb * 64 + c4];
            __nv_bfloat162 h01 = __float22bfloat162_rn(make_float2(v.x, v.y));
            __nv_bfloat162 h23 = __float22bfloat162_rn(make_float2(v.z, v.w));
            float2 r01 = __bfloat1622float2(h01);
            float2 r23 = __bfloat1622float2(h23);
            __nv_bfloat162 l01 = __float22bfloat162_rn(make_float2(v.x - r01.x, v.y - r01.y));
            __nv_bfloat162 l23 = __float22bfloat162_rn(make_float2(v.z - r23.x, v.w - r23.y));
            *(__nv_bfloat162*)&Bh[row * KP + c4]     = h01;
            *(__nv_bfloat162*)&Bh[row * KP + c4 + 2] = h23;
            *(__nv_bfloat162*)&Bl[row * KP + c4]     = l01;
            *(__nv_bfloat162*)&Bl[row * KP + c4 + 2] = l23;
        }
        __syncthreads();

        #pragma unroll
        for (int k16 = 0; k16 < 4; k16++) {
            const int kk = k16 * 16;
            unsigned ah[2][4], al[2][4], bh[4][2], bl[4][2];
            #pragma unroll
            for (int mf = 0; mf < 2; mf++) {
                int r0 = wm * 32 + mf * 16 + lr;
                ah[mf][0] = *(const unsigned*)&Ah[r0 * KP + kk + lc];
                ah[mf][1] = *(const unsigned*)&Ah[(r0 + 8) * KP + kk + lc];
                ah[mf][2] = *(const unsigned*)&Ah[r0 * KP + kk + 8 + lc];
                ah[mf][3] = *(const unsigned*)&Ah[(r0 + 8) * KP + kk + 8 + lc];
                al[mf][0] = *(const unsigned*)&Al[r0 * KP + kk + lc];
                al[mf][1] = *(const unsigned*)&Al[(r0 + 8) * KP + kk + lc];
                al[mf][2] = *(const unsigned*)&Al[r0 * KP + kk + 8 + lc];
                al[mf][3] = *(const unsigned*)&Al[(r0 + 8) * KP + kk + 8 + lc];
            }
            #pragma unroll
            for (int nf = 0; nf < 4; nf++) {
                int n0 = wn * 32 + nf * 8 + lr;
                bh[nf][0] = *(const unsigned*)&Bh[n0 * KP + kk + lc];
                bh[nf][1] = *(const unsigned*)&Bh[n0 * KP + kk + 8 + lc];
                bl[nf][0] = *(const unsigned*)&Bl[n0 * KP + kk + lc];
                bl[nf][1] = *(const unsigned*)&Bl[n0 * KP + kk + 8 + lc];
            }
            #pragma unroll
            for (int mf = 0; mf < 2; mf++)
                #pragma unroll
                for (int nf = 0; nf < 4; nf++) {
                    float* dd = d[mf][nf];
                    mma_bf16(dd[0], dd[1], dd[2], dd[3],
                             ah[mf][0], ah[mf][1], ah[mf][2], ah[mf][3],
                             bh[nf][0], bh[nf][1]);
                    mma_bf16(dd[0], dd[1], dd[2], dd[3],
                             ah[mf][0], ah[mf][1], ah[mf][2], ah[mf][3],
                             bl[nf][0], bl[nf][1]);
                    mma_bf16(dd[0], dd[1], dd[2], dd[3],
                             al[mf][0], al[mf][1], al[mf][2], al[mf][3],
                             bh[nf][0], bh[nf][1]);
                }
        }
        __syncthreads();
    }

    #pragma unroll
    for (int mf = 0; mf < 2; mf++) {
        size_t m = mrow0 + wm * 32 + mf * 16 + lr;
        #pragma unroll
        for (int nf = 0; nf < 4; nf++) {
            int n = bn + wn * 32 + nf * 8 + lc;
            float2 bv = *(const float2*)&bias[n];
            float2 v0 = make_float2(d[mf][nf][0] + bv.x, d[mf][nf][1] + bv.y);
            float2 v1 = make_float2(d[mf][nf][2] + bv.x, d[mf][nf][3] + bv.y);
            *(float2*)&out[m * G3_ + n]       = v0;
            *(float2*)&out[(m + 8) * G3_ + n] = v1;
        }
    }
}

// ===========================================================================
// Recurrent kernel — R9 structure + chunking: processes steps [t0, t0+CH_).
// For t0>0, h state is reloaded from the output history at t0-1 (bit-exact).
// ===========================================================================
#define RTHREADS 384
#define HPAD 272

__device__ __forceinline__ void st_cluster_f32(unsigned addr, unsigned rank, float v) {
    asm volatile(
        "{ .reg .b32 r; mapa.shared::cluster.u32 r, %0, %1; st.shared::cluster.f32 [r], %2; }"
        :: "r"(addr), "r"(rank), "f"(v) : "memory");
}
__device__ __forceinline__ void mbar_init(unsigned addr, unsigned count) {
    asm volatile("mbarrier.init.shared.b64 [%0], %1;" :: "r"(addr), "r"(count) : "memory");
}
__device__ __forceinline__ void mbar_arrive_peer(unsigned addr, unsigned rank) {
    asm volatile(
        "{ .reg .b32 r; mapa.shared::cluster.u32 r, %0, %1; "
        "mbarrier.arrive.release.cluster.shared::cluster.b64 _, [r]; }"
        :: "r"(addr), "r"(rank) : "memory");
}
__device__ __forceinline__ void mbar_wait_cta(unsigned addr, unsigned parity) {
    asm volatile(
        "{\n\t.reg .pred P1;\n\t"
        "WAIT_%=:\n\t"
        "mbarrier.try_wait.parity.acquire.cta.shared::cta.b64 P1, [%0], %1, 0x989680;\n\t"
        "@P1 bra DONE_%=;\n\t"
        "bra WAIT_%=;\n\t"
        "DONE_%=:\n\t}"
        :: "r"(addr), "r"(parity) : "memory");
}
__device__ __forceinline__ void cluster_barrier() {
    asm volatile("barrier.cluster.arrive.aligned;" ::: "memory");
    asm volatile("barrier.cluster.wait.aligned;"   ::: "memory");
}
__device__ __forceinline__ u64t ffma2(u64t a, u64t b, u64t c) {
    u64t d;
    asm("fma.rn.f32x2 %0, %1, %2, %3;" : "=l"(d) : "l"(a), "l"(b), "l"(c));
    return d;
}
__device__ __forceinline__ u64t add2(u64t a, u64t b) {
    u64t d;
    asm("add.rn.f32x2 %0, %1, %2;" : "=l"(d) : "l"(a), "l"(b));
    return d;
}
__device__ __forceinline__ float hsum2(u64t v) {
    float lo, hi;
    asm("mov.b64 {%0, %1}, %2;" : "=f"(lo), "=f"(hi) : "l"(v));
    return lo + hi;
}
__device__ __forceinline__ float fast_sigmoid(float x) {
    return 1.f / (1.f + __expf(-x));
}
__device__ __forceinline__ float fast_tanh(float x) {
    return 2.f / (1.f + __expf(-2.f * x)) - 1.f;
}

__global__ void __cluster_dims__(4, 1, 1) __launch_bounds__(RTHREADS, 1)
gru_rec_kernel(const float* __restrict__ xg, const float* __restrict__ Whh,
               const float* __restrict__ bhh, float* __restrict__ out, int t0)
{
    const int tid = threadIdx.x;
    const int s   = tid & 3;
    const int rg  = tid >> 2;
    const int b   = blockIdx.x >> 2;
    const int c   = blockIdx.x & 3;

    __shared__ __align__(16) float hb[2][HPAD];
    __shared__ float hgc[192];
    __shared__ float xgs[192];
    __shared__ __align__(8) unsigned long long mbar_s[2];

    u64t w2[2][32];
    #pragma unroll
    for (int q = 0; q < 2; q++) {
        int lr = rg * 2 + q;
        int g  = lr >> 6;
        int jl = lr & 63;
        const ulonglong2* wp =
            (const ulonglong2*)(Whh + (size_t)(g * 256 + c * 64 + jl) * 256 + s * 64);
        #pragma unroll
        for (int k = 0; k < 16; k++) {
            ulonglong2 v = wp[k];
            w2[q][2 * k]     = v.x;
            w2[q][2 * k + 1] = v.y;
        }
    }

    float b_r = 0.f, b_z = 0.f, b_n = 0.f;
    if (tid < 64) {
        b_r = bhh[c * 64 + tid];
        b_z = bhh[256 + c * 64 + tid];
        b_n = bhh[512 + c * 64 + tid];
    }
    for (int i = tid; i < 2 * HPAD; i += RTHREADS)
        hb[0][i] = 0.f;

    const unsigned mb0 = smem_u32(&mbar_s[0]);
    const unsigned mb1 = smem_u32(&mbar_s[1]);
    if (tid == 0) { mbar_init(mb0, 4); mbar_init(mb1, 4); }

    const float* xgb = xg + (size_t)b * T_ * G3_;
    const int xoff = (tid >> 6) * 256 + c * 64 + (tid & 63);
    float xgc = (tid < 192) ? xgb[(size_t)t0 * G3_ + xoff] : 0.f;

    const int jglob = c * 64 + (tid & 63);
    const int pidx  = jglob + ((jglob >> 6) << 2);
    const unsigned addr0 = smem_u32(&hb[0][pidx]);
    const unsigned addr1 = smem_u32(&hb[1][pidx]);
    float hreg = 0.f;

    if (t0 > 0) {
        // reload h state (all 256 values) from output history at t0-1
        const float* hsrc = out + ((size_t)b * T_ + t0 - 1) * H_;
        for (int k = tid; k < 256; k += RTHREADS)
            hb[0][k + ((k >> 6) << 2)] = hsrc[k];
        if (tid < 64) hreg = hsrc[jglob];
    }
    __syncthreads();
    cluster_barrier();

    int ph0 = 0, ph1 = 0;
    int cur = 0;
    const int tend = t0 + CH_;
    for (int t = t0; t < tend; t++) {
        if (t != t0) {
            unsigned wa = cur ? mb1 : mb0;
            int p = cur ? ph1 : ph0;
            mbar_wait_cta(wa, p);
            if (cur) ph1 ^= 1; else ph0 ^= 1;
        }
        if (tid < 192) xgs[tid] = xgc;
        float xgn = 0.f;
        if (tid < 192 && t + 1 < T_)
            xgn = xgb[(size_t)(t + 1) * G3_ + xoff];

        const ulonglong2* h2 = (const ulonglong2*)hb[cur];
        u64t a00 = 0, a01 = 0, a10 = 0, a11 = 0;
        #pragma unroll
        for (int i = 0; i < 16; i++) {
            ulonglong2 hv = h2[s * 17 + i];
            a00 = ffma2(w2[0][2 * i],     hv.x, a00);
            a01 = ffma2(w2[0][2 * i + 1], hv.y, a01);
            a10 = ffma2(w2[1][2 * i],     hv.x, a10);
            a11 = ffma2(w2[1][2 * i + 1], hv.y, a11);
        }
        float acc0 = hsum2(add2(a00, a01));
        float acc1 = hsum2(add2(a10, a11));
        acc0 += __shfl_xor_sync(0xffffffffu, acc0, 1);
        acc0 += __shfl_xor_sync(0xffffffffu, acc0, 2);
        acc1 += __shfl_xor_sync(0xffffffffu, acc1, 1);
        acc1 += __shfl_xor_sync(0xffffffffu, acc1, 2);
        if (s == 0) { hgc[rg * 2] = acc0; hgc[rg * 2 + 1] = acc1; }
        __syncthreads();

        if (tid < 64) {
            float hr = hgc[tid]       + b_r;
            float hz = hgc[64 + tid]  + b_z;
            float hn = hgc[128 + tid] + b_n;
            float xr = xgs[tid], xz = xgs[64 + tid], xn = xgs[128 + tid];
            float r  = fast_sigmoid(xr + hr);
            float z  = fast_sigmoid(xz + hz);
            float nn = fast_tanh(xn + r * hn);
            float hnew = (1.f - z) * nn + z * hreg;
            hreg = hnew;
            unsigned dsta = cur ? addr0 : addr1;
            #pragma unroll
            for (int p = 0; p < 4; p++) st_cluster_f32(dsta, p, hnew);
            out[((size_t)b * T_ + t) * H_ + jglob] = hnew;
            asm volatile("bar.sync 3, 64;" ::: "memory");
            if (tid < 4) {
                unsigned am = cur ? mb0 : mb1;
                mbar_arrive_peer(am, (unsigned)tid);
            }
        }

        xgc = xgn;
        cur ^= 1;
    }
    cluster_barrier();
}

// ---------------------------------------------------------------------------
static void launch_rec(cudaStream_t st, const float* xg, const float* Whh,
                       const float* bhh, float* out, int t0)
{
    cudaLaunchConfig_t cfg = {};
    cfg.gridDim  = dim3(B_ * 4, 1, 1);
    cfg.blockDim = dim3(RTHREADS, 1, 1);
    cfg.dynamicSmemBytes = 0;
    cfg.stream = st;
    cudaLaunchAttribute attrs[1];
    attrs[0].id = cudaLaunchAttributeClusterDimension;
    attrs[0].val.clusterDim.x = 4;
    attrs[0].val.clusterDim.y = 1;
    attrs[0].val.clusterDim.z = 1;
    cfg.attrs = attrs;
    cfg.numAttrs = 1;
    cudaLaunchKernelEx(&cfg, gru_rec_kernel, xg, Whh, bhh, out, t0);
}

extern "C" void kernel_launch(void* const* d_in, const int* in_sizes, int n_in,
                              void* d_out, int out_size)
{
    (void)in_sizes; (void)n_in; (void)out_size;
    const float* x   = (const float*)d_in[0];
    const float* Wih = (const float*)d_in[1];
    const float* Whh = (const float*)d_in[2];
    const float* bih = (const float*)d_in[3];
    const float* bhh = (const float*)d_in[4];
    float* out = (float*)d_out;

    float* xg0p; cudaGetSymbolAddress((void**)&xg0p, g_xg0);
    float* xg1p; cudaGetSymbolAddress((void**)&xg1p, g_xg1);
    float* h1p;  cudaGetSymbolAddress((void**)&h1p,  g_h1);

    // One-time infra (no device memory involved): a second stream + events
    // for the cross-layer pipeline. Same objects reused every call; the
    // launched work is identical on every call.
    static cudaStream_t s1 = nullptr;
    static cudaEvent_t evFork, evJoin, evC[NCH_];
    static bool infra_ok = false;
    if (!infra_ok) {
        cudaStreamCreateWithFlags(&s1, cudaStreamNonBlocking);
        cudaEventCreateWithFlags(&evFork, cudaEventDisableTiming);
        cudaEventCreateWithFlags(&evJoin, cudaEventDisableTiming);
        for (int i = 0; i < NCH_; i++)
            cudaEventCreateWithFlags(&evC[i], cudaEventDisableTiming);
        cudaFuncSetAttribute(gemm_tc_kernel,
                             cudaFuncAttributeMaxDynamicSharedMemorySize, SM_TOT);
        infra_ok = true;
    }

    // Fork s1 off the (captured) default stream.
    cudaEventRecord(evFork, 0);
    cudaStreamWaitEvent(s1, evFork, 0);

    // Stream 0: layer-0 input GEMM (full T), then layer-0 rec chunks.
    {
        dim3 g0(B_ * (T_ / 128), G3_ / 64);
        gemm_tc_kernel<<<g0, GT, SM_TOT, 0>>>(x, Wih, bih, xg0p, 0, T_ / 128);
    }
    for (int i = 0; i < NCH_; i++) {
        launch_rec(0, xg0p, Whh, bhh, h1p, i * CH_);
        cudaEventRecord(evC[i], 0);
    }

    // Stream 1: per chunk, layer-1 input GEMM then layer-1 rec chunk.
    const float* Wih1 = Wih + (size_t)G3_ * D_;
    const float* Whh1 = Whh + (size_t)G3_ * H_;
    const float* bih1 = bih + G3_;
    const float* bhh1 = bhh + G3_;
    for (int i = 0; i < NCH_; i++) {
        cudaStreamWaitEvent(s1, evC[i], 0);
        dim3 g1(B_ * (CH_ / 128), G3_ / 64);
        gemm_tc_kernel<<<g1, GT, SM_TOT, s1>>>(h1p, Wih1, bih1, xg1p,
                                               i * CH_, CH_ / 128);
        launch_rec(s1, xg1p, Whh1, bhh1, out, i * CH_);
    }

    // Join back to the captured stream.
    cudaEventRecord(evJoin, s1);
    cudaStreamWaitEvent(0, evJoin, 0);
}

// round 12
// speedup vs baseline: 1.3463x; 1.1041x over previous
#include <cuda_runtime.h>
#include <cuda_bf16.h>
#include <cstdint>

#define B_  32
#define T_  2048
#define D_  256
#define H_  256
#define G3_ 768
#define CH_  256                 // chunk length (steps)
#define NCH_ (T_ / CH_)          // 8 chunks

// Scratch (no cudaMalloc allowed)
__device__ float g_xg0[(size_t)B_ * T_ * G3_];   // layer-0 input gates
__device__ float g_xg1[(size_t)B_ * T_ * G3_];   // layer-1 input gates
__device__ float g_h1 [(size_t)B_ * T_ * H_];    // layer-0 output history

typedef unsigned long long u64t;

__device__ __forceinline__ unsigned smem_u32(const void* p) {
    unsigned a;
    asm("{ .reg .u64 t; cvta.to.shared.u64 t, %1; cvt.u32.u64 %0, t; }"
        : "=r"(a) : "l"(p));
    return a;
}

// ===========================================================================
// Tensor-core GEMM via baseline mma.sync (bf16, split hi/lo, 3-term).
// UNCHANGED from R10 (passing).
// ===========================================================================
#define GT 256
#define KP 72
#define SM_AH 0
#define SM_AL 18432
#define SM_BH 36864
#define SM_BL 46080
#define SM_TOT 55296

__device__ __forceinline__ void mma_bf16(float& d0, float& d1, float& d2, float& d3,
                                         unsigned a0, unsigned a1, unsigned a2, unsigned a3,
                                         unsigned b0, unsigned b1) {
    asm volatile(
        "mma.sync.aligned.m16n8k16.row.col.f32.bf16.bf16.f32 "
        "{%0,%1,%2,%3}, {%4,%5,%6,%7}, {%8,%9}, {%0,%1,%2,%3};"
        : "+f"(d0), "+f"(d1), "+f"(d2), "+f"(d3)
        : "r"(a0), "r"(a1), "r"(a2), "r"(a3), "r"(b0), "r"(b1));
}

__global__ void __launch_bounds__(GT)
gemm_tc_kernel(const float* __restrict__ A, const float* __restrict__ W,
               const float* __restrict__ bias, float* __restrict__ out,
               int t0, int bpb)
{
    extern __shared__ char smem[];
    __nv_bfloat16* Ah = (__nv_bfloat16*)(smem + SM_AH);
    __nv_bfloat16* Al = (__nv_bfloat16*)(smem + SM_AL);
    __nv_bfloat16* Bh = (__nv_bfloat16*)(smem + SM_BH);
    __nv_bfloat16* Bl = (__nv_bfloat16*)(smem + SM_BL);

    const int tid  = threadIdx.x;
    const int lane = tid & 31;
    const int w    = tid >> 5;
    const int wm   = w & 3;
    const int wn   = w >> 2;
    const int bb   = blockIdx.x / bpb;
    const size_t mrow0 = (size_t)bb * T_ + t0 + (size_t)(blockIdx.x % bpb) * 128;
    const int bn   = blockIdx.y * 64;

    const int lr = lane >> 2;
    const int lc = (lane & 3) * 2;

    float d[2][4][4];
    #pragma unroll
    for (int mf = 0; mf < 2; mf++)
        #pragma unroll
        for (int nf = 0; nf < 4; nf++)
            #pragma unroll
            for (int e = 0; e < 4; e++) d[mf][nf][e] = 0.f;

    for (int kb = 0; kb < 4; kb++) {
        #pragma unroll
        for (int i = 0; i < 8; i++) {
            int idx = tid + i * GT;
            int row = idx >> 4;
            int c4  = (idx & 15) * 4;
            float4 v = *(const float4*)&A[(mrow0 + row) * 256 + kb * 64 + c4];
            __nv_bfloat162 h01 = __float22bfloat162_rn(make_float2(v.x, v.y));
            __nv_bfloat162 h23 = __float22bfloat162_rn(make_float2(v.z, v.w));
            float2 r01 = __bfloat1622float2(h01);
            float2 r23 = __bfloat1622float2(h23);
            __nv_bfloat162 l01 = __float22bfloat162_rn(make_float2(v.x - r01.x, v.y - r01.y));
            __nv_bfloat162 l23 = __float22bfloat162_rn(make_float2(v.z - r23.x, v.w - r23.y));
            *(__nv_bfloat162*)&Ah[row * KP + c4]     = h01;
            *(__nv_bfloat162*)&Ah[row * KP + c4 + 2] = h23;
            *(__nv_bfloat162*)&Al[row * KP + c4]     = l01;
            *(__nv_bfloat162*)&Al[row * KP + c4 + 2] = l23;
        }
        #pragma unroll
        for (int i = 0; i < 4; i++) {
            int idx = tid + i * GT;
            int row = idx >> 4;
            int c4  = (idx & 15) * 4;
            float4 v = *(const float4*)&W[(size_t)(bn + row) * 256 + kb * 64 + c4];
            __nv_bfloat162 h01 = __float22bfloat162_rn(make_float2(v.x, v.y));
            __nv_bfloat162 h23 = __float22bfloat162_rn(make_float2(v.z, v.w));
            float2 r01 = __bfloat1622float2(h01);
            float2 r23 = __bfloat1622float2(h23);
            __nv_bfloat162 l01 = __float22bfloat162_rn(make_float2(v.x - r01.x, v.y - r01.y));
            __nv_bfloat162 l23 = __float22bfloat162_rn(make_float2(v.z - r23.x, v.w - r23.y));
            *(__nv_bfloat162*)&Bh[row * KP + c4]     = h01;
            *(__nv_bfloat162*)&Bh[row * KP + c4 + 2] = h23;
            *(__nv_bfloat162*)&Bl[row * KP + c4]     = l01;
            *(__nv_bfloat162*)&Bl[row * KP + c4 + 2] = l23;
        }
        __syncthreads();

        #pragma unroll
        for (int k16 = 0; k16 < 4; k16++) {
            const int kk = k16 * 16;
            unsigned ah[2][4], al[2][4], bh[4][2], bl[4][2];
            #pragma unroll
            for (int mf = 0; mf < 2; mf++) {
                int r0 = wm * 32 + mf * 16 + lr;
                ah[mf][0] = *(const unsigned*)&Ah[r0 * KP + kk + lc];
                ah[mf][1] = *(const unsigned*)&Ah[(r0 + 8) * KP + kk + lc];
                ah[mf][2] = *(const unsigned*)&Ah[r0 * KP + kk + 8 + lc];
                ah[mf][3] = *(const unsigned*)&Ah[(r0 + 8) * KP + kk + 8 + lc];
                al[mf][0] = *(const unsigned*)&Al[r0 * KP + kk + lc];
                al[mf][1] = *(const unsigned*)&Al[(r0 + 8) * KP + kk + lc];
                al[mf][2] = *(const unsigned*)&Al[r0 * KP + kk + 8 + lc];
                al[mf][3] = *(const unsigned*)&Al[(r0 + 8) * KP + kk + 8 + lc];
            }
            #pragma unroll
            for (int nf = 0; nf < 4; nf++) {
                int n0 = wn * 32 + nf * 8 + lr;
                bh[nf][0] = *(const unsigned*)&Bh[n0 * KP + kk + lc];
                bh[nf][1] = *(const unsigned*)&Bh[n0 * KP + kk + 8 + lc];
                bl[nf][0] = *(const unsigned*)&Bl[n0 * KP + kk + lc];
                bl[nf][1] = *(const unsigned*)&Bl[n0 * KP + kk + 8 + lc];
            }
            #pragma unroll
            for (int mf = 0; mf < 2; mf++)
                #pragma unroll
                for (int nf = 0; nf < 4; nf++) {
                    float* dd = d[mf][nf];
                    mma_bf16(dd[0], dd[1], dd[2], dd[3],
                             ah[mf][0], ah[mf][1], ah[mf][2], ah[mf][3],
                             bh[nf][0], bh[nf][1]);
                    mma_bf16(dd[0], dd[1], dd[2], dd[3],
                             ah[mf][0], ah[mf][1], ah[mf][2], ah[mf][3],
                             bl[nf][0], bl[nf][1]);
                    mma_bf16(dd[0], dd[1], dd[2], dd[3],
                             al[mf][0], al[mf][1], al[mf][2], al[mf][3],
                             bh[nf][0], bh[nf][1]);
                }
        }
        __syncthreads();
    }

    #pragma unroll
    for (int mf = 0; mf < 2; mf++) {
        size_t m = mrow0 + wm * 32 + mf * 16 + lr;
        #pragma unroll
        for (int nf = 0; nf < 4; nf++) {
            int n = bn + wn * 32 + nf * 8 + lc;
            float2 bv = *(const float2*)&bias[n];
            float2 v0 = make_float2(d[mf][nf][0] + bv.x, d[mf][nf][1] + bv.y);
            float2 v1 = make_float2(d[mf][nf][2] + bv.x, d[mf][nf][3] + bv.y);
            *(float2*)&out[m * G3_ + n]       = v0;
            *(float2*)&out[(m + 8) * G3_ + n] = v1;
        }
    }
}

// ===========================================================================
// Recurrent kernel — TWO batches per 4-CTA cluster (grid 64 = 16 clusters).
// Weight registers are shared between the two batches; only GEMV issue work
// doubles. All latency-bound step components paid once per batch-PAIR.
// ===========================================================================
#define RTHREADS 384
#define HPAD 272

__device__ __forceinline__ void st_cluster_f32(unsigned addr, unsigned rank, float v) {
    asm volatile(
        "{ .reg .b32 r; mapa.shared::cluster.u32 r, %0, %1; st.shared::cluster.f32 [r], %2; }"
        :: "r"(addr), "r"(rank), "f"(v) : "memory");
}
__device__ __forceinline__ void mbar_init(unsigned addr, unsigned count) {
    asm volatile("mbarrier.init.shared.b64 [%0], %1;" :: "r"(addr), "r"(count) : "memory");
}
__device__ __forceinline__ void mbar_arrive_peer(unsigned addr, unsigned rank) {
    asm volatile(
        "{ .reg .b32 r; mapa.shared::cluster.u32 r, %0, %1; "
        "mbarrier.arrive.release.cluster.shared::cluster.b64 _, [r]; }"
        :: "r"(addr), "r"(rank) : "memory");
}
__device__ __forceinline__ void mbar_wait_cta(unsigned addr, unsigned parity) {
    asm volatile(
        "{\n\t.reg .pred P1;\n\t"
        "WAIT_%=:\n\t"
        "mbarrier.try_wait.parity.acquire.cta.shared::cta.b64 P1, [%0], %1, 0x989680;\n\t"
        "@P1 bra DONE_%=;\n\t"
        "bra WAIT_%=;\n\t"
        "DONE_%=:\n\t}"
        :: "r"(addr), "r"(parity) : "memory");
}
__device__ __forceinline__ void cluster_barrier() {
    asm volatile("barrier.cluster.arrive.aligned;" ::: "memory");
    asm volatile("barrier.cluster.wait.aligned;"   ::: "memory");
}
__device__ __forceinline__ u64t ffma2(u64t a, u64t b, u64t c) {
    u64t d;
    asm("fma.rn.f32x2 %0, %1, %2, %3;" : "=l"(d) : "l"(a), "l"(b), "l"(c));
    return d;
}
__device__ __forceinline__ u64t add2(u64t a, u64t b) {
    u64t d;
    asm("add.rn.f32x2 %0, %1, %2;" : "=l"(d) : "l"(a), "l"(b));
    return d;
}
__device__ __forceinline__ float hsum2(u64t v) {
    float lo, hi;
    asm("mov.b64 {%0, %1}, %2;" : "=f"(lo), "=f"(hi) : "l"(v));
    return lo + hi;
}
__device__ __forceinline__ float fast_sigmoid(float x) {
    return 1.f / (1.f + __expf(-x));
}
__device__ __forceinline__ float fast_tanh(float x) {
    return 2.f / (1.f + __expf(-2.f * x)) - 1.f;
}

__global__ void __cluster_dims__(4, 1, 1) __launch_bounds__(RTHREADS, 1)
gru_rec_kernel(const float* __restrict__ xg, const float* __restrict__ Whh,
               const float* __restrict__ bhh, float* __restrict__ out, int t0)
{
    const int tid = threadIdx.x;
    const int s   = tid & 3;
    const int rg  = tid >> 2;
    const int b0  = (blockIdx.x >> 2) * 2;     // this cluster's two batches
    const int c   = blockIdx.x & 3;

    __shared__ __align__(16) float hb[2][2][HPAD];  // [buf][bt][...]
    __shared__ float hgc[2][192];
    __shared__ float xgs[2][192];
    __shared__ __align__(8) unsigned long long mbar_s[2];

    u64t w2[2][32];
    #pragma unroll
    for (int q = 0; q < 2; q++) {
        int lr = rg * 2 + q;
        int g  = lr >> 6;
        int jl = lr & 63;
        const ulonglong2* wp =
            (const ulonglong2*)(Whh + (size_t)(g * 256 + c * 64 + jl) * 256 + s * 64);
        #pragma unroll
        for (int k = 0; k < 16; k++) {
            ulonglong2 v = wp[k];
            w2[q][2 * k]     = v.x;
            w2[q][2 * k + 1] = v.y;
        }
    }

    const int bt  = (tid >> 6) & 1;            // gate-thread batch (tid<128)
    const int jl6 = tid & 63;
    const int jglob = c * 64 + jl6;
    float b_r = 0.f, b_z = 0.f, b_n = 0.f;
    if (tid < 128) {
        b_r = bhh[jglob];
        b_z = bhh[256 + jglob];
        b_n = bhh[512 + jglob];
    }
    for (int i = tid; i < 4 * HPAD; i += RTHREADS)
        ((float*)hb)[i] = 0.f;

    const unsigned mb0 = smem_u32(&mbar_s[0]);
    const unsigned mb1 = smem_u32(&mbar_s[1]);
    if (tid == 0) { mbar_init(mb0, 4); mbar_init(mb1, 4); }

    const float* xgb0 = xg + (size_t)b0 * T_ * G3_;
    const float* xgb1 = xg + (size_t)(b0 + 1) * T_ * G3_;
    const int xoff = (tid >> 6) * 256 + (tid & 63) + c * 64;   // (g,j) for tid<192
    float xgc0 = 0.f, xgc1 = 0.f;
    if (tid < 192) {
        xgc0 = xgb0[(size_t)t0 * G3_ + xoff];
        xgc1 = xgb1[(size_t)t0 * G3_ + xoff];
    }

    const int pidx = jglob + ((jglob >> 6) << 2);
    const unsigned addr0 = smem_u32(&hb[0][bt][pidx]);
    const unsigned addr1 = smem_u32(&hb[1][bt][pidx]);
    float hreg = 0.f;

    if (t0 > 0) {
        for (int k = tid; k < 512; k += RTHREADS) {
            int kb = k >> 8, kk = k & 255;
            hb[0][kb][kk + ((kk >> 6) << 2)] =
                out[((size_t)(b0 + kb) * T_ + t0 - 1) * H_ + kk];
        }
        if (tid < 128)
            hreg = out[((size_t)(b0 + bt) * T_ + t0 - 1) * H_ + jglob];
    }
    __syncthreads();
    cluster_barrier();

    int ph0 = 0, ph1 = 0;
    int cur = 0;
    const int tend = t0 + CH_;
    for (int t = t0; t < tend; t++) {
        if (t != t0) {
            unsigned wa = cur ? mb1 : mb0;
            int p = cur ? ph1 : ph0;
            mbar_wait_cta(wa, p);
            if (cur) ph1 ^= 1; else ph0 ^= 1;
        }
        if (tid < 192) { xgs[0][tid] = xgc0; xgs[1][tid] = xgc1; }
        float xgn0 = 0.f, xgn1 = 0.f;
        if (tid < 192 && t + 1 < T_) {
            xgn0 = xgb0[(size_t)(t + 1) * G3_ + xoff];
            xgn1 = xgb1[(size_t)(t + 1) * G3_ + xoff];
        }

        // GEMV for both batches (weights shared; accumulators reused per bt)
        #pragma unroll
        for (int bq = 0; bq < 2; bq++) {
            const ulonglong2* h2 = (const ulonglong2*)hb[cur][bq];
            u64t a00 = 0, a01 = 0, a10 = 0, a11 = 0;
            #pragma unroll
            for (int i = 0; i < 16; i++) {
                ulonglong2 hv = h2[s * 17 + i];
                a00 = ffma2(w2[0][2 * i],     hv.x, a00);
                a01 = ffma2(w2[0][2 * i + 1], hv.y, a01);
                a10 = ffma2(w2[1][2 * i],     hv.x, a10);
                a11 = ffma2(w2[1][2 * i + 1], hv.y, a11);
            }
            float acc0 = hsum2(add2(a00, a01));
            float acc1 = hsum2(add2(a10, a11));
            acc0 += __shfl_xor_sync(0xffffffffu, acc0, 1);
            acc0 += __shfl_xor_sync(0xffffffffu, acc0, 2);
            acc1 += __shfl_xor_sync(0xffffffffu, acc1, 1);
            acc1 += __shfl_xor_sync(0xffffffffu, acc1, 2);
            if (s == 0) { hgc[bq][rg * 2] = acc0; hgc[bq][rg * 2 + 1] = acc1; }
        }
        __syncthreads();

        if (tid < 128) {
            float hr = hgc[bt][jl6]       + b_r;
            float hz = hgc[bt][64 + jl6]  + b_z;
            float hn = hgc[bt][128 + jl6] + b_n;
            float xr = xgs[bt][jl6], xz = xgs[bt][64 + jl6], xn = xgs[bt][128 + jl6];
            float r  = fast_sigmoid(xr + hr);
            float z  = fast_sigmoid(xz + hz);
            float nn = fast_tanh(xn + r * hn);
            float hnew = (1.f - z) * nn + z * hreg;
            hreg = hnew;
            unsigned dsta = cur ? addr0 : addr1;
            #pragma unroll
            for (int p = 0; p < 4; p++) st_cluster_f32(dsta, p, hnew);
            out[((size_t)(b0 + bt) * T_ + t) * H_ + jglob] = hnew;
            asm volatile("bar.sync 3, 128;" ::: "memory");
            if (tid < 4) {
                unsigned am = cur ? mb0 : mb1;
                mbar_arrive_peer(am, (unsigned)tid);
            }
        }

        xgc0 = xgn0; xgc1 = xgn1;
        cur ^= 1;
    }
    cluster_barrier();
}

// ---------------------------------------------------------------------------
static void launch_rec(cudaStream_t st, const float* xg, const float* Whh,
                       const float* bhh, float* out, int t0)
{
    cudaLaunchConfig_t cfg = {};
    cfg.gridDim  = dim3((B_ / 2) * 4, 1, 1);   // 64 CTAs = 16 clusters
    cfg.blockDim = dim3(RTHREADS, 1, 1);
    cfg.dynamicSmemBytes = 0;
    cfg.stream = st;
    cudaLaunchAttribute attrs[1];
    attrs[0].id = cudaLaunchAttributeClusterDimension;
    attrs[0].val.clusterDim.x = 4;
    attrs[0].val.clusterDim.y = 1;
    attrs[0].val.clusterDim.z = 1;
    cfg.attrs = attrs;
    cfg.numAttrs = 1;
    cudaLaunchKernelEx(&cfg, gru_rec_kernel, xg, Whh, bhh, out, t0);
}

extern "C" void kernel_launch(void* const* d_in, const int* in_sizes, int n_in,
                              void* d_out, int out_size)
{
    (void)in_sizes; (void)n_in; (void)out_size;
    const float* x   = (const float*)d_in[0];
    const float* Wih = (const float*)d_in[1];
    const float* Whh = (const float*)d_in[2];
    const float* bih = (const float*)d_in[3];
    const float* bhh = (const float*)d_in[4];
    float* out = (float*)d_out;

    float* xg0p; cudaGetSymbolAddress((void**)&xg0p, g_xg0);
    float* xg1p; cudaGetSymbolAddress((void**)&xg1p, g_xg1);
    float* h1p;  cudaGetSymbolAddress((void**)&h1p,  g_h1);

    static cudaStream_t s1 = nullptr;
    static cudaEvent_t evFork, evJoin, evC[NCH_];
    static bool infra_ok = false;
    if (!infra_ok) {
        cudaStreamCreateWithFlags(&s1, cudaStreamNonBlocking);
        cudaEventCreateWithFlags(&evFork, cudaEventDisableTiming);
        cudaEventCreateWithFlags(&evJoin, cudaEventDisableTiming);
        for (int i = 0; i < NCH_; i++)
            cudaEventCreateWithFlags(&evC[i], cudaEventDisableTiming);
        cudaFuncSetAttribute(gemm_tc_kernel,
                             cudaFuncAttributeMaxDynamicSharedMemorySize, SM_TOT);
        infra_ok = true;
    }

    cudaEventRecord(evFork, 0);
    cudaStreamWaitEvent(s1, evFork, 0);

    // Stream 0: layer-0 input GEMM (full T), then layer-0 rec chunks.
    {
        dim3 g0(B_ * (T_ / 128), G3_ / 64);
        gemm_tc_kernel<<<g0, GT, SM_TOT, 0>>>(x, Wih, bih, xg0p, 0, T_ / 128);
    }
    for (int i = 0; i < NCH_; i++) {
        launch_rec(0, xg0p, Whh, bhh, h1p, i * CH_);
        cudaEventRecord(evC[i], 0);
    }

    // Stream 1: per chunk, layer-1 input GEMM then layer-1 rec chunk.
    const float* Wih1 = Wih + (size_t)G3_ * D_;
    const float* Whh1 = Whh + (size_t)G3_ * H_;
    const float* bih1 = bih + G3_;
    const float* bhh1 = bhh + G3_;
    for (int i = 0; i < NCH_; i++) {
        cudaStreamWaitEvent(s1, evC[i], 0);
        dim3 g1(B_ * (CH_ / 128), G3_ / 64);
        gemm_tc_kernel<<<g1, GT, SM_TOT, s1>>>(h1p, Wih1, bih1, xg1p,
                                               i * CH_, CH_ / 128);
        launch_rec(s1, xg1p, Whh1, bhh1, out, i * CH_);
    }

    cudaEventRecord(evJoin, s1);
    cudaStreamWaitEvent(0, evJoin, 0);
}

// round 13
// speedup vs baseline: 1.4374x; 1.0676x over previous
#include <cuda_runtime.h>
#include <cuda_bf16.h>
#include <cstdint>

#define B_  32
#define T_  2048
#define D_  256
#define H_  256
#define G3_ 768
#define CH_  128                 // chunk length (steps)
#define NCH_ (T_ / CH_)          // 16 chunks

// Scratch (no cudaMalloc allowed)
__device__ float g_xg0[(size_t)B_ * T_ * G3_];   // layer-0 input gates
__device__ float g_xg1[(size_t)B_ * T_ * G3_];   // layer-1 input gates
__device__ float g_h1 [(size_t)B_ * T_ * H_];    // layer-0 output history

typedef unsigned long long u64t;

__device__ __forceinline__ unsigned smem_u32(const void* p) {
    unsigned a;
    asm("{ .reg .u64 t; cvta.to.shared.u64 t, %1; cvt.u32.u64 %0, t; }"
        : "=r"(a) : "l"(p));
    return a;
}

// ===========================================================================
// Tensor-core GEMM via baseline mma.sync (bf16, split hi/lo, 3-term).
// UNCHANGED math from R10/R11 (passing).
// ===========================================================================
#define GT 256
#define KP 72
#define SM_AH 0
#define SM_AL 18432
#define SM_BH 36864
#define SM_BL 46080
#define SM_TOT 55296

__device__ __forceinline__ void mma_bf16(float& d0, float& d1, float& d2, float& d3,
                                         unsigned a0, unsigned a1, unsigned a2, unsigned a3,
                                         unsigned b0, unsigned b1) {
    asm volatile(
        "mma.sync.aligned.m16n8k16.row.col.f32.bf16.bf16.f32 "
        "{%0,%1,%2,%3}, {%4,%5,%6,%7}, {%8,%9}, {%0,%1,%2,%3};"
        : "+f"(d0), "+f"(d1), "+f"(d2), "+f"(d3)
        : "r"(a0), "r"(a1), "r"(a2), "r"(a3), "r"(b0), "r"(b1));
}

__global__ void __launch_bounds__(GT)
gemm_tc_kernel(const float* __restrict__ A, const float* __restrict__ W,
               const float* __restrict__ bias, float* __restrict__ out,
               int t0, int bpb)
{
    extern __shared__ char smem[];
    __nv_bfloat16* Ah = (__nv_bfloat16*)(smem + SM_AH);
    __nv_bfloat16* Al = (__nv_bfloat16*)(smem + SM_AL);
    __nv_bfloat16* Bh = (__nv_bfloat16*)(smem + SM_BH);
    __nv_bfloat16* Bl = (__nv_bfloat16*)(smem + SM_BL);

    const int tid  = threadIdx.x;
    const int lane = tid & 31;
    const int w    = tid >> 5;
    const int wm   = w & 3;
    const int wn   = w >> 2;
    const int bb   = blockIdx.x / bpb;
    const size_t mrow0 = (size_t)bb * T_ + t0 + (size_t)(blockIdx.x % bpb) * 128;
    const int bn   = blockIdx.y * 64;

    const int lr = lane >> 2;
    const int lc = (lane & 3) * 2;

    float d[2][4][4];
    #pragma unroll
    for (int mf = 0; mf < 2; mf++)
        #pragma unroll
        for (int nf = 0; nf < 4; nf++)
            #pragma unroll
            for (int e = 0; e < 4; e++) d[mf][nf][e] = 0.f;

    for (int kb = 0; kb < 4; kb++) {
        #pragma unroll
        for (int i = 0; i < 8; i++) {
            int idx = tid + i * GT;
            int row = idx >> 4;
            int c4  = (idx & 15) * 4;
            float4 v = *(const float4*)&A[(mrow0 + row) * 256 + kb * 64 + c4];
            __nv_bfloat162 h01 = __float22bfloat162_rn(make_float2(v.x, v.y));
            __nv_bfloat162 h23 = __float22bfloat162_rn(make_float2(v.z, v.w));
            float2 r01 = __bfloat1622float2(h01);
            float2 r23 = __bfloat1622float2(h23);
            __nv_bfloat162 l01 = __float22bfloat162_rn(make_float2(v.x - r01.x, v.y - r01.y));
            __nv_bfloat162 l23 = __float22bfloat162_rn(make_float2(v.z - r23.x, v.w - r23.y));
            *(__nv_bfloat162*)&Ah[row * KP + c4]     = h01;
            *(__nv_bfloat162*)&Ah[row * KP + c4 + 2] = h23;
            *(__nv_bfloat162*)&Al[row * KP + c4]     = l01;
            *(__nv_bfloat162*)&Al[row * KP + c4 + 2] = l23;
        }
        #pragma unroll
        for (int i = 0; i < 4; i++) {
            int idx = tid + i * GT;
            int row = idx >> 4;
            int c4  = (idx & 15) * 4;
            float4 v = *(const float4*)&W[(size_t)(bn + row) * 256 + kb * 64 + c4];
            __nv_bfloat162 h01 = __float22bfloat162_rn(make_float2(v.x, v.y));
            __nv_bfloat162 h23 = __float22bfloat162_rn(make_float2(v.z, v.w));
            float2 r01 = __bfloat1622float2(h01);
            float2 r23 = __bfloat1622float2(h23);
            __nv_bfloat162 l01 = __float22bfloat162_rn(make_float2(v.x - r01.x, v.y - r01.y));
            __nv_bfloat162 l23 = __float22bfloat162_rn(make_float2(v.z - r23.x, v.w - r23.y));
            *(__nv_bfloat162*)&Bh[row * KP + c4]     = h01;
            *(__nv_bfloat162*)&Bh[row * KP + c4 + 2] = h23;
            *(__nv_bfloat162*)&Bl[row * KP + c4]     = l01;
            *(__nv_bfloat162*)&Bl[row * KP + c4 + 2] = l23;
        }
        __syncthreads();

        #pragma unroll
        for (int k16 = 0; k16 < 4; k16++) {
            const int kk = k16 * 16;
            unsigned ah[2][4], al[2][4], bh[4][2], bl[4][2];
            #pragma unroll
            for (int mf = 0; mf < 2; mf++) {
                int r0 = wm * 32 + mf * 16 + lr;
                ah[mf][0] = *(const unsigned*)&Ah[r0 * KP + kk + lc];
                ah[mf][1] = *(const unsigned*)&Ah[(r0 + 8) * KP + kk + lc];
                ah[mf][2] = *(const unsigned*)&Ah[r0 * KP + kk + 8 + lc];
                ah[mf][3] = *(const unsigned*)&Ah[(r0 + 8) * KP + kk + 8 + lc];
                al[mf][0] = *(const unsigned*)&Al[r0 * KP + kk + lc];
                al[mf][1] = *(const unsigned*)&Al[(r0 + 8) * KP + kk + lc];
                al[mf][2] = *(const unsigned*)&Al[r0 * KP + kk + 8 + lc];
                al[mf][3] = *(const unsigned*)&Al[(r0 + 8) * KP + kk + 8 + lc];
            }
            #pragma unroll
            for (int nf = 0; nf < 4; nf++) {
                int n0 = wn * 32 + nf * 8 + lr;
                bh[nf][0] = *(const unsigned*)&Bh[n0 * KP + kk + lc];
                bh[nf][1] = *(const unsigned*)&Bh[n0 * KP + kk + 8 + lc];
                bl[nf][0] = *(const unsigned*)&Bl[n0 * KP + kk + lc];
                bl[nf][1] = *(const unsigned*)&Bl[n0 * KP + kk + 8 + lc];
            }
            #pragma unroll
            for (int mf = 0; mf < 2; mf++)
                #pragma unroll
                for (int nf = 0; nf < 4; nf++) {
                    float* dd = d[mf][nf];
                    mma_bf16(dd[0], dd[1], dd[2], dd[3],
                             ah[mf][0], ah[mf][1], ah[mf][2], ah[mf][3],
                             bh[nf][0], bh[nf][1]);
                    mma_bf16(dd[0], dd[1], dd[2], dd[3],
                             ah[mf][0], ah[mf][1], ah[mf][2], ah[mf][3],
                             bl[nf][0], bl[nf][1]);
                    mma_bf16(dd[0], dd[1], dd[2], dd[3],
                             al[mf][0], al[mf][1], al[mf][2], al[mf][3],
                             bh[nf][0], bh[nf][1]);
                }
        }
        __syncthreads();
    }

    #pragma unroll
    for (int mf = 0; mf < 2; mf++) {
        size_t m = mrow0 + wm * 32 + mf * 16 + lr;
        #pragma unroll
        for (int nf = 0; nf < 4; nf++) {
            int n = bn + wn * 32 + nf * 8 + lc;
            float2 bv = *(const float2*)&bias[n];
            float2 v0 = make_float2(d[mf][nf][0] + bv.x, d[mf][nf][1] + bv.y);
            float2 v1 = make_float2(d[mf][nf][2] + bv.x, d[mf][nf][3] + bv.y);
            *(float2*)&out[m * G3_ + n]       = v0;
            *(float2*)&out[(m + 8) * G3_ + n] = v1;
        }
    }
}

// ===========================================================================
// Recurrent kernel — TWO batches per 4-CTA cluster (grid 64 = 16 clusters).
// R12: the two batches' GEMV chains are manually interleaved (8 independent
// FFMA2 accumulators sharing each h-load pair) for ILP.
// ===========================================================================
#define RTHREADS 384
#define HPAD 272

__device__ __forceinline__ void st_cluster_f32(unsigned addr, unsigned rank, float v) {
    asm volatile(
        "{ .reg .b32 r; mapa.shared::cluster.u32 r, %0, %1; st.shared::cluster.f32 [r], %2; }"
        :: "r"(addr), "r"(rank), "f"(v) : "memory");
}
__device__ __forceinline__ void mbar_init(unsigned addr, unsigned count) {
    asm volatile("mbarrier.init.shared.b64 [%0], %1;" :: "r"(addr), "r"(count) : "memory");
}
__device__ __forceinline__ void mbar_arrive_peer(unsigned addr, unsigned rank) {
    asm volatile(
        "{ .reg .b32 r; mapa.shared::cluster.u32 r, %0, %1; "
        "mbarrier.arrive.release.cluster.shared::cluster.b64 _, [r]; }"
        :: "r"(addr), "r"(rank) : "memory");
}
__device__ __forceinline__ void mbar_wait_cta(unsigned addr, unsigned parity) {
    asm volatile(
        "{\n\t.reg .pred P1;\n\t"
        "WAIT_%=:\n\t"
        "mbarrier.try_wait.parity.acquire.cta.shared::cta.b64 P1, [%0], %1, 0x989680;\n\t"
        "@P1 bra DONE_%=;\n\t"
        "bra WAIT_%=;\n\t"
        "DONE_%=:\n\t}"
        :: "r"(addr), "r"(parity) : "memory");
}
__device__ __forceinline__ void cluster_barrier() {
    asm volatile("barrier.cluster.arrive.aligned;" ::: "memory");
    asm volatile("barrier.cluster.wait.aligned;"   ::: "memory");
}
__device__ __forceinline__ u64t ffma2(u64t a, u64t b, u64t c) {
    u64t d;
    asm("fma.rn.f32x2 %0, %1, %2, %3;" : "=l"(d) : "l"(a), "l"(b), "l"(c));
    return d;
}
__device__ __forceinline__ u64t add2(u64t a, u64t b) {
    u64t d;
    asm("add.rn.f32x2 %0, %1, %2;" : "=l"(d) : "l"(a), "l"(b));
    return d;
}
__device__ __forceinline__ float hsum2(u64t v) {
    float lo, hi;
    asm("mov.b64 {%0, %1}, %2;" : "=f"(lo), "=f"(hi) : "l"(v));
    return lo + hi;
}
__device__ __forceinline__ float fast_sigmoid(float x) {
    return 1.f / (1.f + __expf(-x));
}
__device__ __forceinline__ float fast_tanh(float x) {
    return 2.f / (1.f + __expf(-2.f * x)) - 1.f;
}

__global__ void __cluster_dims__(4, 1, 1) __launch_bounds__(RTHREADS, 1)
gru_rec_kernel(const float* __restrict__ xg, const float* __restrict__ Whh,
               const float* __restrict__ bhh, float* __restrict__ out, int t0)
{
    const int tid = threadIdx.x;
    const int s   = tid & 3;
    const int rg  = tid >> 2;
    const int b0  = (blockIdx.x >> 2) * 2;
    const int c   = blockIdx.x & 3;

    __shared__ __align__(16) float hb[2][2][HPAD];  // [buf][bt][...]
    __shared__ float hgc[2][192];
    __shared__ float xgs[2][192];
    __shared__ __align__(8) unsigned long long mbar_s[2];

    u64t w2[2][32];
    #pragma unroll
    for (int q = 0; q < 2; q++) {
        int lr = rg * 2 + q;
        int g  = lr >> 6;
        int jl = lr & 63;
        const ulonglong2* wp =
            (const ulonglong2*)(Whh + (size_t)(g * 256 + c * 64 + jl) * 256 + s * 64);
        #pragma unroll
        for (int k = 0; k < 16; k++) {
            ulonglong2 v = wp[k];
            w2[q][2 * k]     = v.x;
            w2[q][2 * k + 1] = v.y;
        }
    }

    const int bt  = (tid >> 6) & 1;
    const int jl6 = tid & 63;
    const int jglob = c * 64 + jl6;
    float b_r = 0.f, b_z = 0.f, b_n = 0.f;
    if (tid < 128) {
        b_r = bhh[jglob];
        b_z = bhh[256 + jglob];
        b_n = bhh[512 + jglob];
    }
    for (int i = tid; i < 4 * HPAD; i += RTHREADS)
        ((float*)hb)[i] = 0.f;

    const unsigned mb0 = smem_u32(&mbar_s[0]);
    const unsigned mb1 = smem_u32(&mbar_s[1]);
    if (tid == 0) { mbar_init(mb0, 4); mbar_init(mb1, 4); }

    const float* xgb0 = xg + (size_t)b0 * T_ * G3_;
    const float* xgb1 = xg + (size_t)(b0 + 1) * T_ * G3_;
    const int xoff = (tid >> 6) * 256 + (tid & 63) + c * 64;
    float xgc0 = 0.f, xgc1 = 0.f;
    if (tid < 192) {
        xgc0 = xgb0[(size_t)t0 * G3_ + xoff];
        xgc1 = xgb1[(size_t)t0 * G3_ + xoff];
    }

    const int pidx = jglob + ((jglob >> 6) << 2);
    const unsigned addr0 = smem_u32(&hb[0][bt][pidx]);
    const unsigned addr1 = smem_u32(&hb[1][bt][pidx]);
    float hreg = 0.f;

    if (t0 > 0) {
        for (int k = tid; k < 512; k += RTHREADS) {
            int kb = k >> 8, kk = k & 255;
            hb[0][kb][kk + ((kk >> 6) << 2)] =
                out[((size_t)(b0 + kb) * T_ + t0 - 1) * H_ + kk];
        }
        if (tid < 128)
            hreg = out[((size_t)(b0 + bt) * T_ + t0 - 1) * H_ + jglob];
    }
    __syncthreads();
    cluster_barrier();

    int ph0 = 0, ph1 = 0;
    int cur = 0;
    const int tend = t0 + CH_;
    for (int t = t0; t < tend; t++) {
        if (t != t0) {
            unsigned wa = cur ? mb1 : mb0;
            int p = cur ? ph1 : ph0;
            mbar_wait_cta(wa, p);
            if (cur) ph1 ^= 1; else ph0 ^= 1;
        }
        if (tid < 192) { xgs[0][tid] = xgc0; xgs[1][tid] = xgc1; }
        float xgn0 = 0.f, xgn1 = 0.f;
        if (tid < 192 && t + 1 < T_) {
            xgn0 = xgb0[(size_t)(t + 1) * G3_ + xoff];
            xgn1 = xgb1[(size_t)(t + 1) * G3_ + xoff];
        }

        // GEMV for BOTH batches, interleaved for ILP (weights shared)
        const ulonglong2* h2a = (const ulonglong2*)hb[cur][0];
        const ulonglong2* h2b = (const ulonglong2*)hb[cur][1];
        u64t p00 = 0, p01 = 0, p10 = 0, p11 = 0;   // batch b0
        u64t q00 = 0, q01 = 0, q10 = 0, q11 = 0;   // batch b0+1
        #pragma unroll
        for (int i = 0; i < 16; i++) {
            ulonglong2 ha = h2a[s * 17 + i];
            ulonglong2 hv = h2b[s * 17 + i];
            p00 = ffma2(w2[0][2 * i],     ha.x, p00);
            q00 = ffma2(w2[0][2 * i],     hv.x, q00);
            p01 = ffma2(w2[0][2 * i + 1], ha.y, p01);
            q01 = ffma2(w2[0][2 * i + 1], hv.y, q01);
            p10 = ffma2(w2[1][2 * i],     ha.x, p10);
            q10 = ffma2(w2[1][2 * i],     hv.x, q10);
            p11 = ffma2(w2[1][2 * i + 1], ha.y, p11);
            q11 = ffma2(w2[1][2 * i + 1], hv.y, q11);
        }
        float pa0 = hsum2(add2(p00, p01));
        float pa1 = hsum2(add2(p10, p11));
        float qa0 = hsum2(add2(q00, q01));
        float qa1 = hsum2(add2(q10, q11));
        pa0 += __shfl_xor_sync(0xffffffffu, pa0, 1);
        pa0 += __shfl_xor_sync(0xffffffffu, pa0, 2);
        pa1 += __shfl_xor_sync(0xffffffffu, pa1, 1);
        pa1 += __shfl_xor_sync(0xffffffffu, pa1, 2);
        qa0 += __shfl_xor_sync(0xffffffffu, qa0, 1);
        qa0 += __shfl_xor_sync(0xffffffffu, qa0, 2);
        qa1 += __shfl_xor_sync(0xffffffffu, qa1, 1);
        qa1 += __shfl_xor_sync(0xffffffffu, qa1, 2);
        if (s == 0) {
            hgc[0][rg * 2] = pa0; hgc[0][rg * 2 + 1] = pa1;
            hgc[1][rg * 2] = qa0; hgc[1][rg * 2 + 1] = qa1;
        }
        __syncthreads();

        if (tid < 128) {
            float hr = hgc[bt][jl6]       + b_r;
            float hz = hgc[bt][64 + jl6]  + b_z;
            float hn = hgc[bt][128 + jl6] + b_n;
            float xr = xgs[bt][jl6], xz = xgs[bt][64 + jl6], xn = xgs[bt][128 + jl6];
            float r  = fast_sigmoid(xr + hr);
            float z  = fast_sigmoid(xz + hz);
            float nn = fast_tanh(xn + r * hn);
            float hnew = (1.f - z) * nn + z * hreg;
            hreg = hnew;
            unsigned dsta = cur ? addr0 : addr1;
            #pragma unroll
            for (int p = 0; p < 4; p++) st_cluster_f32(dsta, p, hnew);
            out[((size_t)(b0 + bt) * T_ + t) * H_ + jglob] = hnew;
            asm volatile("bar.sync 3, 128;" ::: "memory");
            if (tid < 4) {
                unsigned am = cur ? mb0 : mb1;
                mbar_arrive_peer(am, (unsigned)tid);
            }
        }

        xgc0 = xgn0; xgc1 = xgn1;
        cur ^= 1;
    }
    cluster_barrier();
}

// ---------------------------------------------------------------------------
static void launch_rec(cudaStream_t st, const float* xg, const float* Whh,
                       const float* bhh, float* out, int t0)
{
    cudaLaunchConfig_t cfg = {};
    cfg.gridDim  = dim3((B_ / 2) * 4, 1, 1);   // 64 CTAs = 16 clusters
    cfg.blockDim = dim3(RTHREADS, 1, 1);
    cfg.dynamicSmemBytes = 0;
    cfg.stream = st;
    cudaLaunchAttribute attrs[1];
    attrs[0].id = cudaLaunchAttributeClusterDimension;
    attrs[0].val.clusterDim.x = 4;
    attrs[0].val.clusterDim.y = 1;
    attrs[0].val.clusterDim.z = 1;
    cfg.attrs = attrs;
    cfg.numAttrs = 1;
    cudaLaunchKernelEx(&cfg, gru_rec_kernel, xg, Whh, bhh, out, t0);
}

extern "C" void kernel_launch(void* const* d_in, const int* in_sizes, int n_in,
                              void* d_out, int out_size)
{
    (void)in_sizes; (void)n_in; (void)out_size;
    const float* x   = (const float*)d_in[0];
    const float* Wih = (const float*)d_in[1];
    const float* Whh = (const float*)d_in[2];
    const float* bih = (const float*)d_in[3];
    const float* bhh = (const float*)d_in[4];
    float* out = (float*)d_out;

    float* xg0p; cudaGetSymbolAddress((void**)&xg0p, g_xg0);
    float* xg1p; cudaGetSymbolAddress((void**)&xg1p, g_xg1);
    float* h1p;  cudaGetSymbolAddress((void**)&h1p,  g_h1);

    static cudaStream_t s1 = nullptr;
    static cudaEvent_t evFork, evJoin, evG, evC[NCH_];
    static bool infra_ok = false;
    if (!infra_ok) {
        cudaStreamCreateWithFlags(&s1, cudaStreamNonBlocking);
        cudaEventCreateWithFlags(&evFork, cudaEventDisableTiming);
        cudaEventCreateWithFlags(&evJoin, cudaEventDisableTiming);
        cudaEventCreateWithFlags(&evG, cudaEventDisableTiming);
        for (int i = 0; i < NCH_; i++)
            cudaEventCreateWithFlags(&evC[i], cudaEventDisableTiming);
        cudaFuncSetAttribute(gemm_tc_kernel,
                             cudaFuncAttributeMaxDynamicSharedMemorySize, SM_TOT);
        infra_ok = true;
    }

    cudaEventRecord(evFork, 0);
    cudaStreamWaitEvent(s1, evFork, 0);

    // Stream 0: gemm0 for chunk 0 only, then rec0 chunk 0 starts immediately.
    {
        dim3 gc0(B_ * (CH_ / 128), G3_ / 64);
        gemm_tc_kernel<<<gc0, GT, SM_TOT, 0>>>(x, Wih, bih, xg0p, 0, CH_ / 128);
    }
    // Stream 1: gemm0 for the REMAINING chunks, overlapped with rec0 chunk 0.
    {
        int bpb = (T_ - CH_) / 128;
        dim3 gcr(B_ * bpb, G3_ / 64);
        gemm_tc_kernel<<<gcr, GT, SM_TOT, s1>>>(x, Wih, bih, xg0p, CH_, bpb);
        cudaEventRecord(evG, s1);
    }

    launch_rec(0, xg0p, Whh, bhh, h1p, 0);
    cudaEventRecord(evC[0], 0);
    cudaStreamWaitEvent(0, evG, 0);          // rest of xg0 ready before chunk 1
    for (int i = 1; i < NCH_; i++) {
        launch_rec(0, xg0p, Whh, bhh, h1p, i * CH_);
        cudaEventRecord(evC[i], 0);
    }

    // Stream 1: per chunk, layer-1 input GEMM then layer-1 rec chunk.
    const float* Wih1 = Wih + (size_t)G3_ * D_;
    const float* Whh1 = Whh + (size_t)G3_ * H_;
    const float* bih1 = bih + G3_;
    const float* bhh1 = bhh + G3_;
    for (int i = 0; i < NCH_; i++) {
        cudaStreamWaitEvent(s1, evC[i], 0);
        dim3 g1(B_ * (CH_ / 128), G3_ / 64);
        gemm_tc_kernel<<<g1, GT, SM_TOT, s1>>>(h1p, Wih1, bih1, xg1p,
                                               i * CH_, CH_ / 128);
        launch_rec(s1, xg1p, Whh1, bhh1, out, i * CH_);
    }

    cudaEventRecord(evJoin, s1);
    cudaStreamWaitEvent(0, evJoin, 0);
}

// round 14
// speedup vs baseline: 1.5366x; 1.0690x over previous
#include <cuda_runtime.h>
#include <cuda_bf16.h>
#include <cstdint>

#define B_  32
#define T_  2048
#define D_  256
#define H_  256
#define G3_ 768
#define CH_  128                 // chunk length (steps)
#define NCH_ (T_ / CH_)          // 16 chunks

// Scratch (no cudaMalloc allowed)
__device__ float g_xg0[(size_t)B_ * T_ * G3_];   // layer-0 input gates
__device__ float g_xg1[(size_t)B_ * T_ * G3_];   // layer-1 input gates
__device__ float g_h1 [(size_t)B_ * T_ * H_];    // layer-0 output history

typedef unsigned long long u64t;

__device__ __forceinline__ unsigned smem_u32(const void* p) {
    unsigned a;
    asm("{ .reg .u64 t; cvta.to.shared.u64 t, %1; cvt.u32.u64 %0, t; }"
        : "=r"(a) : "l"(p));
    return a;
}

// ===========================================================================
// Tensor-core GEMM via baseline mma.sync (bf16, split hi/lo, 3-term).
// UNCHANGED math (passing since R7).
// ===========================================================================
#define GT 256
#define KP 72
#define SM_AH 0
#define SM_AL 18432
#define SM_BH 36864
#define SM_BL 46080
#define SM_TOT 55296

__device__ __forceinline__ void mma_bf16(float& d0, float& d1, float& d2, float& d3,
                                         unsigned a0, unsigned a1, unsigned a2, unsigned a3,
                                         unsigned b0, unsigned b1) {
    asm volatile(
        "mma.sync.aligned.m16n8k16.row.col.f32.bf16.bf16.f32 "
        "{%0,%1,%2,%3}, {%4,%5,%6,%7}, {%8,%9}, {%0,%1,%2,%3};"
        : "+f"(d0), "+f"(d1), "+f"(d2), "+f"(d3)
        : "r"(a0), "r"(a1), "r"(a2), "r"(a3), "r"(b0), "r"(b1));
}

__global__ void __launch_bounds__(GT)
gemm_tc_kernel(const float* __restrict__ A, const float* __restrict__ W,
               const float* __restrict__ bias, float* __restrict__ out,
               int t0, int bpb)
{
    extern __shared__ char smem[];
    __nv_bfloat16* Ah = (__nv_bfloat16*)(smem + SM_AH);
    __nv_bfloat16* Al = (__nv_bfloat16*)(smem + SM_AL);
    __nv_bfloat16* Bh = (__nv_bfloat16*)(smem + SM_BH);
    __nv_bfloat16* Bl = (__nv_bfloat16*)(smem + SM_BL);

    const int tid  = threadIdx.x;
    const int lane = tid & 31;
    const int w    = tid >> 5;
    const int wm   = w & 3;
    const int wn   = w >> 2;
    const int bb   = blockIdx.x / bpb;
    const size_t mrow0 = (size_t)bb * T_ + t0 + (size_t)(blockIdx.x % bpb) * 128;
    const int bn   = blockIdx.y * 64;

    const int lr = lane >> 2;
    const int lc = (lane & 3) * 2;

    float d[2][4][4];
    #pragma unroll
    for (int mf = 0; mf < 2; mf++)
        #pragma unroll
        for (int nf = 0; nf < 4; nf++)
            #pragma unroll
            for (int e = 0; e < 4; e++) d[mf][nf][e] = 0.f;

    for (int kb = 0; kb < 4; kb++) {
        #pragma unroll
        for (int i = 0; i < 8; i++) {
            int idx = tid + i * GT;
            int row = idx >> 4;
            int c4  = (idx & 15) * 4;
            float4 v = *(const float4*)&A[(mrow0 + row) * 256 + kb * 64 + c4];
            __nv_bfloat162 h01 = __float22bfloat162_rn(make_float2(v.x, v.y));
            __nv_bfloat162 h23 = __float22bfloat162_rn(make_float2(v.z, v.w));
            float2 r01 = __bfloat1622float2(h01);
            float2 r23 = __bfloat1622float2(h23);
            __nv_bfloat162 l01 = __float22bfloat162_rn(make_float2(v.x - r01.x, v.y - r01.y));
            __nv_bfloat162 l23 = __float22bfloat162_rn(make_float2(v.z - r23.x, v.w - r23.y));
            *(__nv_bfloat162*)&Ah[row * KP + c4]     = h01;
            *(__nv_bfloat162*)&Ah[row * KP + c4 + 2] = h23;
            *(__nv_bfloat162*)&Al[row * KP + c4]     = l01;
            *(__nv_bfloat162*)&Al[row * KP + c4 + 2] = l23;
        }
        #pragma unroll
        for (int i = 0; i < 4; i++) {
            int idx = tid + i * GT;
            int row = idx >> 4;
            int c4  = (idx & 15) * 4;
            float4 v = *(const float4*)&W[(size_t)(bn + row) * 256 + kb * 64 + c4];
            __nv_bfloat162 h01 = __float22bfloat162_rn(make_float2(v.x, v.y));
            __nv_bfloat162 h23 = __float22bfloat162_rn(make_float2(v.z, v.w));
            float2 r01 = __bfloat1622float2(h01);
            float2 r23 = __bfloat1622float2(h23);
            __nv_bfloat162 l01 = __float22bfloat162_rn(make_float2(v.x - r01.x, v.y - r01.y));
            __nv_bfloat162 l23 = __float22bfloat162_rn(make_float2(v.z - r23.x, v.w - r23.y));
            *(__nv_bfloat162*)&Bh[row * KP + c4]     = h01;
            *(__nv_bfloat162*)&Bh[row * KP + c4 + 2] = h23;
            *(__nv_bfloat162*)&Bl[row * KP + c4]     = l01;
            *(__nv_bfloat162*)&Bl[row * KP + c4 + 2] = l23;
        }
        __syncthreads();

        #pragma unroll
        for (int k16 = 0; k16 < 4; k16++) {
            const int kk = k16 * 16;
            unsigned ah[2][4], al[2][4], bh[4][2], bl[4][2];
            #pragma unroll
            for (int mf = 0; mf < 2; mf++) {
                int r0 = wm * 32 + mf * 16 + lr;
                ah[mf][0] = *(const unsigned*)&Ah[r0 * KP + kk + lc];
                ah[mf][1] = *(const unsigned*)&Ah[(r0 + 8) * KP + kk + lc];
                ah[mf][2] = *(const unsigned*)&Ah[r0 * KP + kk + 8 + lc];
                ah[mf][3] = *(const unsigned*)&Ah[(r0 + 8) * KP + kk + 8 + lc];
                al[mf][0] = *(const unsigned*)&Al[r0 * KP + kk + lc];
                al[mf][1] = *(const unsigned*)&Al[(r0 + 8) * KP + kk + lc];
                al[mf][2] = *(const unsigned*)&Al[r0 * KP + kk + 8 + lc];
                al[mf][3] = *(const unsigned*)&Al[(r0 + 8) * KP + kk + 8 + lc];
            }
            #pragma unroll
            for (int nf = 0; nf < 4; nf++) {
                int n0 = wn * 32 + nf * 8 + lr;
                bh[nf][0] = *(const unsigned*)&Bh[n0 * KP + kk + lc];
                bh[nf][1] = *(const unsigned*)&Bh[n0 * KP + kk + 8 + lc];
                bl[nf][0] = *(const unsigned*)&Bl[n0 * KP + kk + lc];
                bl[nf][1] = *(const unsigned*)&Bl[n0 * KP + kk + 8 + lc];
            }
            #pragma unroll
            for (int mf = 0; mf < 2; mf++)
                #pragma unroll
                for (int nf = 0; nf < 4; nf++) {
                    float* dd = d[mf][nf];
                    mma_bf16(dd[0], dd[1], dd[2], dd[3],
                             ah[mf][0], ah[mf][1], ah[mf][2], ah[mf][3],
                             bh[nf][0], bh[nf][1]);
                    mma_bf16(dd[0], dd[1], dd[2], dd[3],
                             ah[mf][0], ah[mf][1], ah[mf][2], ah[mf][3],
                             bl[nf][0], bl[nf][1]);
                    mma_bf16(dd[0], dd[1], dd[2], dd[3],
                             al[mf][0], al[mf][1], al[mf][2], al[mf][3],
                             bh[nf][0], bh[nf][1]);
                }
        }
        __syncthreads();
    }

    #pragma unroll
    for (int mf = 0; mf < 2; mf++) {
        size_t m = mrow0 + wm * 32 + mf * 16 + lr;
        #pragma unroll
        for (int nf = 0; nf < 4; nf++) {
            int n = bn + wn * 32 + nf * 8 + lc;
            float2 bv = *(const float2*)&bias[n];
            float2 v0 = make_float2(d[mf][nf][0] + bv.x, d[mf][nf][1] + bv.y);
            float2 v1 = make_float2(d[mf][nf][2] + bv.x, d[mf][nf][3] + bv.y);
            *(float2*)&out[m * G3_ + n]       = v0;
            *(float2*)&out[(m + 8) * G3_ + n] = v1;
        }
    }
}

// ===========================================================================
// Recurrent kernel — BYTE-IDENTICAL to R12 (two batches per 4-CTA cluster,
// interleaved GEMV). Only the launch graph changed this round.
// ===========================================================================
#define RTHREADS 384
#define HPAD 272

__device__ __forceinline__ void st_cluster_f32(unsigned addr, unsigned rank, float v) {
    asm volatile(
        "{ .reg .b32 r; mapa.shared::cluster.u32 r, %0, %1; st.shared::cluster.f32 [r], %2; }"
        :: "r"(addr), "r"(rank), "f"(v) : "memory");
}
__device__ __forceinline__ void mbar_init(unsigned addr, unsigned count) {
    asm volatile("mbarrier.init.shared.b64 [%0], %1;" :: "r"(addr), "r"(count) : "memory");
}
__device__ __forceinline__ void mbar_arrive_peer(unsigned addr, unsigned rank) {
    asm volatile(
        "{ .reg .b32 r; mapa.shared::cluster.u32 r, %0, %1; "
        "mbarrier.arrive.release.cluster.shared::cluster.b64 _, [r]; }"
        :: "r"(addr), "r"(rank) : "memory");
}
__device__ __forceinline__ void mbar_wait_cta(unsigned addr, unsigned parity) {
    asm volatile(
        "{\n\t.reg .pred P1;\n\t"
        "WAIT_%=:\n\t"
        "mbarrier.try_wait.parity.acquire.cta.shared::cta.b64 P1, [%0], %1, 0x989680;\n\t"
        "@P1 bra DONE_%=;\n\t"
        "bra WAIT_%=;\n\t"
        "DONE_%=:\n\t}"
        :: "r"(addr), "r"(parity) : "memory");
}
__device__ __forceinline__ void cluster_barrier() {
    asm volatile("barrier.cluster.arrive.aligned;" ::: "memory");
    asm volatile("barrier.cluster.wait.aligned;"   ::: "memory");
}
__device__ __forceinline__ u64t ffma2(u64t a, u64t b, u64t c) {
    u64t d;
    asm("fma.rn.f32x2 %0, %1, %2, %3;" : "=l"(d) : "l"(a), "l"(b), "l"(c));
    return d;
}
__device__ __forceinline__ u64t add2(u64t a, u64t b) {
    u64t d;
    asm("add.rn.f32x2 %0, %1, %2;" : "=l"(d) : "l"(a), "l"(b));
    return d;
}
__device__ __forceinline__ float hsum2(u64t v) {
    float lo, hi;
    asm("mov.b64 {%0, %1}, %2;" : "=f"(lo), "=f"(hi) : "l"(v));
    return lo + hi;
}
__device__ __forceinline__ float fast_sigmoid(float x) {
    return 1.f / (1.f + __expf(-x));
}
__device__ __forceinline__ float fast_tanh(float x) {
    return 2.f / (1.f + __expf(-2.f * x)) - 1.f;
}

__global__ void __cluster_dims__(4, 1, 1) __launch_bounds__(RTHREADS, 1)
gru_rec_kernel(const float* __restrict__ xg, const float* __restrict__ Whh,
               const float* __restrict__ bhh, float* __restrict__ out, int t0)
{
    const int tid = threadIdx.x;
    const int s   = tid & 3;
    const int rg  = tid >> 2;
    const int b0  = (blockIdx.x >> 2) * 2;
    const int c   = blockIdx.x & 3;

    __shared__ __align__(16) float hb[2][2][HPAD];
    __shared__ float hgc[2][192];
    __shared__ float xgs[2][192];
    __shared__ __align__(8) unsigned long long mbar_s[2];

    u64t w2[2][32];
    #pragma unroll
    for (int q = 0; q < 2; q++) {
        int lr = rg * 2 + q;
        int g  = lr >> 6;
        int jl = lr & 63;
        const ulonglong2* wp =
            (const ulonglong2*)(Whh + (size_t)(g * 256 + c * 64 + jl) * 256 + s * 64);
        #pragma unroll
        for (int k = 0; k < 16; k++) {
            ulonglong2 v = wp[k];
            w2[q][2 * k]     = v.x;
            w2[q][2 * k + 1] = v.y;
        }
    }

    const int bt  = (tid >> 6) & 1;
    const int jl6 = tid & 63;
    const int jglob = c * 64 + jl6;
    float b_r = 0.f, b_z = 0.f, b_n = 0.f;
    if (tid < 128) {
        b_r = bhh[jglob];
        b_z = bhh[256 + jglob];
        b_n = bhh[512 + jglob];
    }
    for (int i = tid; i < 4 * HPAD; i += RTHREADS)
        ((float*)hb)[i] = 0.f;

    const unsigned mb0 = smem_u32(&mbar_s[0]);
    const unsigned mb1 = smem_u32(&mbar_s[1]);
    if (tid == 0) { mbar_init(mb0, 4); mbar_init(mb1, 4); }

    const float* xgb0 = xg + (size_t)b0 * T_ * G3_;
    const float* xgb1 = xg + (size_t)(b0 + 1) * T_ * G3_;
    const int xoff = (tid >> 6) * 256 + (tid & 63) + c * 64;
    float xgc0 = 0.f, xgc1 = 0.f;
    if (tid < 192) {
        xgc0 = xgb0[(size_t)t0 * G3_ + xoff];
        xgc1 = xgb1[(size_t)t0 * G3_ + xoff];
    }

    const int pidx = jglob + ((jglob >> 6) << 2);
    const unsigned addr0 = smem_u32(&hb[0][bt][pidx]);
    const unsigned addr1 = smem_u32(&hb[1][bt][pidx]);
    float hreg = 0.f;

    if (t0 > 0) {
        for (int k = tid; k < 512; k += RTHREADS) {
            int kb = k >> 8, kk = k & 255;
            hb[0][kb][kk + ((kk >> 6) << 2)] =
                out[((size_t)(b0 + kb) * T_ + t0 - 1) * H_ + kk];
        }
        if (tid < 128)
            hreg = out[((size_t)(b0 + bt) * T_ + t0 - 1) * H_ + jglob];
    }
    __syncthreads();
    cluster_barrier();

    int ph0 = 0, ph1 = 0;
    int cur = 0;
    const int tend = t0 + CH_;
    for (int t = t0; t < tend; t++) {
        if (t != t0) {
            unsigned wa = cur ? mb1 : mb0;
            int p = cur ? ph1 : ph0;
            mbar_wait_cta(wa, p);
            if (cur) ph1 ^= 1; else ph0 ^= 1;
        }
        if (tid < 192) { xgs[0][tid] = xgc0; xgs[1][tid] = xgc1; }
        float xgn0 = 0.f, xgn1 = 0.f;
        if (tid < 192 && t + 1 < T_) {
            xgn0 = xgb0[(size_t)(t + 1) * G3_ + xoff];
            xgn1 = xgb1[(size_t)(t + 1) * G3_ + xoff];
        }

        const ulonglong2* h2a = (const ulonglong2*)hb[cur][0];
        const ulonglong2* h2b = (const ulonglong2*)hb[cur][1];
        u64t p00 = 0, p01 = 0, p10 = 0, p11 = 0;
        u64t q00 = 0, q01 = 0, q10 = 0, q11 = 0;
        #pragma unroll
        for (int i = 0; i < 16; i++) {
            ulonglong2 ha = h2a[s * 17 + i];
            ulonglong2 hv = h2b[s * 17 + i];
            p00 = ffma2(w2[0][2 * i],     ha.x, p00);
            q00 = ffma2(w2[0][2 * i],     hv.x, q00);
            p01 = ffma2(w2[0][2 * i + 1], ha.y, p01);
            q01 = ffma2(w2[0][2 * i + 1], hv.y, q01);
            p10 = ffma2(w2[1][2 * i],     ha.x, p10);
            q10 = ffma2(w2[1][2 * i],     hv.x, q10);
            p11 = ffma2(w2[1][2 * i + 1], ha.y, p11);
            q11 = ffma2(w2[1][2 * i + 1], hv.y, q11);
        }
        float pa0 = hsum2(add2(p00, p01));
        float pa1 = hsum2(add2(p10, p11));
        float qa0 = hsum2(add2(q00, q01));
        float qa1 = hsum2(add2(q10, q11));
        pa0 += __shfl_xor_sync(0xffffffffu, pa0, 1);
        pa0 += __shfl_xor_sync(0xffffffffu, pa0, 2);
        pa1 += __shfl_xor_sync(0xffffffffu, pa1, 1);
        pa1 += __shfl_xor_sync(0xffffffffu, pa1, 2);
        qa0 += __shfl_xor_sync(0xffffffffu, qa0, 1);
        qa0 += __shfl_xor_sync(0xffffffffu, qa0, 2);
        qa1 += __shfl_xor_sync(0xffffffffu, qa1, 1);
        qa1 += __shfl_xor_sync(0xffffffffu, qa1, 2);
        if (s == 0) {
            hgc[0][rg * 2] = pa0; hgc[0][rg * 2 + 1] = pa1;
            hgc[1][rg * 2] = qa0; hgc[1][rg * 2 + 1] = qa1;
        }
        __syncthreads();

        if (tid < 128) {
            float hr = hgc[bt][jl6]       + b_r;
            float hz = hgc[bt][64 + jl6]  + b_z;
            float hn = hgc[bt][128 + jl6] + b_n;
            float xr = xgs[bt][jl6], xz = xgs[bt][64 + jl6], xn = xgs[bt][128 + jl6];
            float r  = fast_sigmoid(xr + hr);
            float z  = fast_sigmoid(xz + hz);
            float nn = fast_tanh(xn + r * hn);
            float hnew = (1.f - z) * nn + z * hreg;
            hreg = hnew;
            unsigned dsta = cur ? addr0 : addr1;
            #pragma unroll
            for (int p = 0; p < 4; p++) st_cluster_f32(dsta, p, hnew);
            out[((size_t)(b0 + bt) * T_ + t) * H_ + jglob] = hnew;
            asm volatile("bar.sync 3, 128;" ::: "memory");
            if (tid < 4) {
                unsigned am = cur ? mb0 : mb1;
                mbar_arrive_peer(am, (unsigned)tid);
            }
        }

        xgc0 = xgn0; xgc1 = xgn1;
        cur ^= 1;
    }
    cluster_barrier();
}

// ---------------------------------------------------------------------------
static void launch_rec(cudaStream_t st, const float* xg, const float* Whh,
                       const float* bhh, float* out, int t0)
{
    cudaLaunchConfig_t cfg = {};
    cfg.gridDim  = dim3((B_ / 2) * 4, 1, 1);   // 64 CTAs = 16 clusters
    cfg.blockDim = dim3(RTHREADS, 1, 1);
    cfg.dynamicSmemBytes = 0;
    cfg.stream = st;
    cudaLaunchAttribute attrs[1];
    attrs[0].id = cudaLaunchAttributeClusterDimension;
    attrs[0].val.clusterDim.x = 4;
    attrs[0].val.clusterDim.y = 1;
    attrs[0].val.clusterDim.z = 1;
    cfg.attrs = attrs;
    cfg.numAttrs = 1;
    cudaLaunchKernelEx(&cfg, gru_rec_kernel, xg, Whh, bhh, out, t0);
}

extern "C" void kernel_launch(void* const* d_in, const int* in_sizes, int n_in,
                              void* d_out, int out_size)
{
    (void)in_sizes; (void)n_in; (void)out_size;
    const float* x   = (const float*)d_in[0];
    const float* Wih = (const float*)d_in[1];
    const float* Whh = (const float*)d_in[2];
    const float* bih = (const float*)d_in[3];
    const float* bhh = (const float*)d_in[4];
    float* out = (float*)d_out;

    float* xg0p; cudaGetSymbolAddress((void**)&xg0p, g_xg0);
    float* xg1p; cudaGetSymbolAddress((void**)&xg1p, g_xg1);
    float* h1p;  cudaGetSymbolAddress((void**)&h1p,  g_h1);

    // Streams: 0 = rec layer 0; s1 = rec layer 1; s2 = ALL overlapped GEMMs.
    static cudaStream_t s1 = nullptr, s2 = nullptr;
    static cudaEvent_t evFork, evJoin, evG0, evC[NCH_], evG1[NCH_];
    static bool infra_ok = false;
    if (!infra_ok) {
        cudaStreamCreateWithFlags(&s1, cudaStreamNonBlocking);
        cudaStreamCreateWithFlags(&s2, cudaStreamNonBlocking);
        cudaEventCreateWithFlags(&evFork, cudaEventDisableTiming);
        cudaEventCreateWithFlags(&evJoin, cudaEventDisableTiming);
        cudaEventCreateWithFlags(&evG0, cudaEventDisableTiming);
        for (int i = 0; i < NCH_; i++) {
            cudaEventCreateWithFlags(&evC[i], cudaEventDisableTiming);
            cudaEventCreateWithFlags(&evG1[i], cudaEventDisableTiming);
        }
        cudaFuncSetAttribute(gemm_tc_kernel,
                             cudaFuncAttributeMaxDynamicSharedMemorySize, SM_TOT);
        infra_ok = true;
    }

    cudaEventRecord(evFork, 0);
    cudaStreamWaitEvent(s1, evFork, 0);
    cudaStreamWaitEvent(s2, evFork, 0);

    // gemm0 chunk 0 on stream 0 (rec0_c0 needs it immediately).
    {
        dim3 gc0(B_ * (CH_ / 128), G3_ / 64);
        gemm_tc_kernel<<<gc0, GT, SM_TOT, 0>>>(x, Wih, bih, xg0p, 0, CH_ / 128);
    }
    // gemm0 remainder on s2, overlapped with rec0_c0.
    {
        int bpb = (T_ - CH_) / 128;
        dim3 gcr(B_ * bpb, G3_ / 64);
        gemm_tc_kernel<<<gcr, GT, SM_TOT, s2>>>(x, Wih, bih, xg0p, CH_, bpb);
        cudaEventRecord(evG0, s2);
    }

    // Stream 0: layer-0 rec chain.
    launch_rec(0, xg0p, Whh, bhh, h1p, 0);
    cudaEventRecord(evC[0], 0);
    cudaStreamWaitEvent(0, evG0, 0);         // rest of xg0 ready before chunk 1
    for (int i = 1; i < NCH_; i++) {
        launch_rec(0, xg0p, Whh, bhh, h1p, i * CH_);
        cudaEventRecord(evC[i], 0);
    }

    // s2: layer-1 GEMM per chunk (depends only on rec0_ci); s1: layer-1 rec.
    const float* Wih1 = Wih + (size_t)G3_ * D_;
    const float* Whh1 = Whh + (size_t)G3_ * H_;
    const float* bih1 = bih + G3_;
    const float* bhh1 = bhh + G3_;
    for (int i = 0; i < NCH_; i++) {
        cudaStreamWaitEvent(s2, evC[i], 0);
        dim3 g1(B_ * (CH_ / 128), G3_ / 64);
        gemm_tc_kernel<<<g1, GT, SM_TOT, s2>>>(h1p, Wih1, bih1, xg1p,
                                               i * CH_, CH_ / 128);
        cudaEventRecord(evG1[i], s2);
        cudaStreamWaitEvent(s1, evG1[i], 0);
        launch_rec(s1, xg1p, Whh1, bhh1, out, i * CH_);
    }

    cudaEventRecord(evJoin, s1);
    cudaStreamWaitEvent(0, evJoin, 0);
}

// round 15
// speedup vs baseline: 1.5609x; 1.0158x over previous
#include <cuda_runtime.h>
#include <cuda_bf16.h>
#include <cstdint>

#define B_  32
#define T_  2048
#define D_  256
#define H_  256
#define G3_ 768
#define CH_  128                 // chunk length (steps)
#define NCH_ (T_ / CH_)          // 16 chunks

// Scratch (no cudaMalloc allowed)
__device__ float g_xg0[(size_t)B_ * T_ * G3_];
__device__ float g_xg1[(size_t)B_ * T_ * G3_];
__device__ float g_h1 [(size_t)B_ * T_ * H_];
// Progress counters (reset by cudaMemsetAsync at graph start each replay)
__device__ int g_cnt_g0;            // gemm0_rest CTAs done (target 5760)
__device__ int g_rec0prog[16];      // rec0 chunks done, per cluster
__device__ int g_cnt_g1[NCH_];      // gemm1 chunk i CTAs done (target 384)

typedef unsigned long long u64t;

__device__ __forceinline__ unsigned smem_u32(const void* p) {
    unsigned a;
    asm("{ .reg .u64 t; cvta.to.shared.u64 t, %1; cvt.u32.u64 %0, t; }"
        : "=r"(a) : "l"(p));
    return a;
}

// ===========================================================================
// Tensor-core GEMM (bf16 split hi/lo, 3-term) + optional device-side gate
// (spin on rec0 progress) and completion counter.
// ===========================================================================
#define GT 256
#define KP 72
#define SM_AH 0
#define SM_AL 18432
#define SM_BH 36864
#define SM_BL 46080
#define SM_TOT 55296

__device__ __forceinline__ void mma_bf16(float& d0, float& d1, float& d2, float& d3,
                                         unsigned a0, unsigned a1, unsigned a2, unsigned a3,
                                         unsigned b0, unsigned b1) {
    asm volatile(
        "mma.sync.aligned.m16n8k16.row.col.f32.bf16.bf16.f32 "
        "{%0,%1,%2,%3}, {%4,%5,%6,%7}, {%8,%9}, {%0,%1,%2,%3};"
        : "+f"(d0), "+f"(d1), "+f"(d2), "+f"(d3)
        : "r"(a0), "r"(a1), "r"(a2), "r"(a3), "r"(b0), "r"(b1));
}

__global__ void __launch_bounds__(GT)
gemm_tc_kernel(const float* __restrict__ A, const float* __restrict__ W,
               const float* __restrict__ bias, float* __restrict__ out,
               int t0, int bpb,
               const int* wait_arr, int wait_val, int* done_cnt)
{
    extern __shared__ char smem[];
    __nv_bfloat16* Ah = (__nv_bfloat16*)(smem + SM_AH);
    __nv_bfloat16* Al = (__nv_bfloat16*)(smem + SM_AL);
    __nv_bfloat16* Bh = (__nv_bfloat16*)(smem + SM_BH);
    __nv_bfloat16* Bl = (__nv_bfloat16*)(smem + SM_BL);

    const int tid  = threadIdx.x;
    const int lane = tid & 31;
    const int w    = tid >> 5;
    const int wm   = w & 3;
    const int wn   = w >> 2;
    const int bb   = blockIdx.x / bpb;
    const size_t mrow0 = (size_t)bb * T_ + t0 + (size_t)(blockIdx.x % bpb) * 128;
    const int bn   = blockIdx.y * 64;

    // Gate: wait until rec0 has produced this batch-pair's chunk.
    if (wait_arr) {
        if (tid == 0) {
            const volatile int* p = wait_arr + (bb >> 1);
            while (*p < wait_val) {}
            __threadfence();
        }
        __syncthreads();
    }

    const int lr = lane >> 2;
    const int lc = (lane & 3) * 2;

    float d[2][4][4];
    #pragma unroll
    for (int mf = 0; mf < 2; mf++)
        #pragma unroll
        for (int nf = 0; nf < 4; nf++)
            #pragma unroll
            for (int e = 0; e < 4; e++) d[mf][nf][e] = 0.f;

    for (int kb = 0; kb < 4; kb++) {
        #pragma unroll
        for (int i = 0; i < 8; i++) {
            int idx = tid + i * GT;
            int row = idx >> 4;
            int c4  = (idx & 15) * 4;
            float4 v = *(const float4*)&A[(mrow0 + row) * 256 + kb * 64 + c4];
            __nv_bfloat162 h01 = __float22bfloat162_rn(make_float2(v.x, v.y));
            __nv_bfloat162 h23 = __float22bfloat162_rn(make_float2(v.z, v.w));
            float2 r01 = __bfloat1622float2(h01);
            float2 r23 = __bfloat1622float2(h23);
            __nv_bfloat162 l01 = __float22bfloat162_rn(make_float2(v.x - r01.x, v.y - r01.y));
            __nv_bfloat162 l23 = __float22bfloat162_rn(make_float2(v.z - r23.x, v.w - r23.y));
            *(__nv_bfloat162*)&Ah[row * KP + c4]     = h01;
            *(__nv_bfloat162*)&Ah[row * KP + c4 + 2] = h23;
            *(__nv_bfloat162*)&Al[row * KP + c4]     = l01;
            *(__nv_bfloat162*)&Al[row * KP + c4 + 2] = l23;
        }
        #pragma unroll
        for (int i = 0; i < 4; i++) {
            int idx = tid + i * GT;
            int row = idx >> 4;
            int c4  = (idx & 15) * 4;
            float4 v = *(const float4*)&W[(size_t)(bn + row) * 256 + kb * 64 + c4];
            __nv_bfloat162 h01 = __float22bfloat162_rn(make_float2(v.x, v.y));
            __nv_bfloat162 h23 = __float22bfloat162_rn(make_float2(v.z, v.w));
            float2 r01 = __bfloat1622float2(h01);
            float2 r23 = __bfloat1622float2(h23);
            __nv_bfloat162 l01 = __float22bfloat162_rn(make_float2(v.x - r01.x, v.y - r01.y));
            __nv_bfloat162 l23 = __float22bfloat162_rn(make_float2(v.z - r23.x, v.w - r23.y));
            *(__nv_bfloat162*)&Bh[row * KP + c4]     = h01;
            *(__nv_bfloat162*)&Bh[row * KP + c4 + 2] = h23;
            *(__nv_bfloat162*)&Bl[row * KP + c4]     = l01;
            *(__nv_bfloat162*)&Bl[row * KP + c4 + 2] = l23;
        }
        __syncthreads();

        #pragma unroll
        for (int k16 = 0; k16 < 4; k16++) {
            const int kk = k16 * 16;
            unsigned ah[2][4], al[2][4], bh[4][2], bl[4][2];
            #pragma unroll
            for (int mf = 0; mf < 2; mf++) {
                int r0 = wm * 32 + mf * 16 + lr;
                ah[mf][0] = *(const unsigned*)&Ah[r0 * KP + kk + lc];
                ah[mf][1] = *(const unsigned*)&Ah[(r0 + 8) * KP + kk + lc];
                ah[mf][2] = *(const unsigned*)&Ah[r0 * KP + kk + 8 + lc];
                ah[mf][3] = *(const unsigned*)&Ah[(r0 + 8) * KP + kk + 8 + lc];
                al[mf][0] = *(const unsigned*)&Al[r0 * KP + kk + lc];
                al[mf][1] = *(const unsigned*)&Al[(r0 + 8) * KP + kk + lc];
                al[mf][2] = *(const unsigned*)&Al[r0 * KP + kk + 8 + lc];
                al[mf][3] = *(const unsigned*)&Al[(r0 + 8) * KP + kk + 8 + lc];
            }
            #pragma unroll
            for (int nf = 0; nf < 4; nf++) {
                int n0 = wn * 32 + nf * 8 + lr;
                bh[nf][0] = *(const unsigned*)&Bh[n0 * KP + kk + lc];
                bh[nf][1] = *(const unsigned*)&Bh[n0 * KP + kk + 8 + lc];
                bl[nf][0] = *(const unsigned*)&Bl[n0 * KP + kk + lc];
                bl[nf][1] = *(const unsigned*)&Bl[n0 * KP + kk + 8 + lc];
            }
            #pragma unroll
            for (int mf = 0; mf < 2; mf++)
                #pragma unroll
                for (int nf = 0; nf < 4; nf++) {
                    float* dd = d[mf][nf];
                    mma_bf16(dd[0], dd[1], dd[2], dd[3],
                             ah[mf][0], ah[mf][1], ah[mf][2], ah[mf][3],
                             bh[nf][0], bh[nf][1]);
                    mma_bf16(dd[0], dd[1], dd[2], dd[3],
                             ah[mf][0], ah[mf][1], ah[mf][2], ah[mf][3],
                             bl[nf][0], bl[nf][1]);
                    mma_bf16(dd[0], dd[1], dd[2], dd[3],
                             al[mf][0], al[mf][1], al[mf][2], al[mf][3],
                             bh[nf][0], bh[nf][1]);
                }
        }
        __syncthreads();
    }

    #pragma unroll
    for (int mf = 0; mf < 2; mf++) {
        size_t m = mrow0 + wm * 32 + mf * 16 + lr;
        #pragma unroll
        for (int nf = 0; nf < 4; nf++) {
            int n = bn + wn * 32 + nf * 8 + lc;
            float2 bv = *(const float2*)&bias[n];
            float2 v0 = make_float2(d[mf][nf][0] + bv.x, d[mf][nf][1] + bv.y);
            float2 v1 = make_float2(d[mf][nf][2] + bv.x, d[mf][nf][3] + bv.y);
            *(float2*)&out[m * G3_ + n]       = v0;
            *(float2*)&out[(m + 8) * G3_ + n] = v1;
        }
    }

    if (done_cnt) {
        __syncthreads();
        if (tid == 0) { __threadfence(); atomicAdd(done_cnt, 1); }
    }
}

// ===========================================================================
// PERSISTENT recurrent kernel: one launch covers all T=2048 steps.
// Same per-step math as R12/R13 (2 batches per 4-CTA cluster, interleaved
// FFMA2 GEMV). Chunk boundaries: spin-gate on input availability + progress
// signal for downstream consumers. Weights/h/pipeline state persist.
// ===========================================================================
#define RTHREADS 384
#define HPAD 272

__device__ __forceinline__ void st_cluster_f32(unsigned addr, unsigned rank, float v) {
    asm volatile(
        "{ .reg .b32 r; mapa.shared::cluster.u32 r, %0, %1; st.shared::cluster.f32 [r], %2; }"
        :: "r"(addr), "r"(rank), "f"(v) : "memory");
}
__device__ __forceinline__ void mbar_init(unsigned addr, unsigned count) {
    asm volatile("mbarrier.init.shared.b64 [%0], %1;" :: "r"(addr), "r"(count) : "memory");
}
__device__ __forceinline__ void mbar_arrive_peer(unsigned addr, unsigned rank) {
    asm volatile(
        "{ .reg .b32 r; mapa.shared::cluster.u32 r, %0, %1; "
        "mbarrier.arrive.release.cluster.shared::cluster.b64 _, [r]; }"
        :: "r"(addr), "r"(rank) : "memory");
}
__device__ __forceinline__ void mbar_wait_cta(unsigned addr, unsigned parity) {
    asm volatile(
        "{\n\t.reg .pred P1;\n\t"
        "WAIT_%=:\n\t"
        "mbarrier.try_wait.parity.acquire.cta.shared::cta.b64 P1, [%0], %1, 0x989680;\n\t"
        "@P1 bra DONE_%=;\n\t"
        "bra WAIT_%=;\n\t"
        "DONE_%=:\n\t}"
        :: "r"(addr), "r"(parity) : "memory");
}
__device__ __forceinline__ void cluster_barrier() {
    asm volatile("barrier.cluster.arrive.aligned;" ::: "memory");
    asm volatile("barrier.cluster.wait.aligned;"   ::: "memory");
}
__device__ __forceinline__ u64t ffma2(u64t a, u64t b, u64t c) {
    u64t d;
    asm("fma.rn.f32x2 %0, %1, %2, %3;" : "=l"(d) : "l"(a), "l"(b), "l"(c));
    return d;
}
__device__ __forceinline__ u64t add2(u64t a, u64t b) {
    u64t d;
    asm("add.rn.f32x2 %0, %1, %2;" : "=l"(d) : "l"(a), "l"(b));
    return d;
}
__device__ __forceinline__ float hsum2(u64t v) {
    float lo, hi;
    asm("mov.b64 {%0, %1}, %2;" : "=f"(lo), "=f"(hi) : "l"(v));
    return lo + hi;
}
__device__ __forceinline__ float fast_sigmoid(float x) {
    return 1.f / (1.f + __expf(-x));
}
__device__ __forceinline__ float fast_tanh(float x) {
    return 2.f / (1.f + __expf(-2.f * x)) - 1.f;
}

__global__ void __cluster_dims__(4, 1, 1) __launch_bounds__(RTHREADS, 1)
gru_rec_kernel(const float* __restrict__ xg, const float* __restrict__ Whh,
               const float* __restrict__ bhh, float* __restrict__ out,
               const int* gate_arr, int gate_target, int gate_per_chunk,
               int* prog_arr)
{
    const int tid = threadIdx.x;
    const int s   = tid & 3;
    const int rg  = tid >> 2;
    const int b0  = (blockIdx.x >> 2) * 2;
    const int c   = blockIdx.x & 3;

    __shared__ __align__(16) float hb[2][2][HPAD];
    __shared__ float hgc[2][192];
    __shared__ float xgs[2][192];
    __shared__ __align__(8) unsigned long long mbar_s[2];

    u64t w2[2][32];
    #pragma unroll
    for (int q = 0; q < 2; q++) {
        int lr = rg * 2 + q;
        int g  = lr >> 6;
        int jl = lr & 63;
        const ulonglong2* wp =
            (const ulonglong2*)(Whh + (size_t)(g * 256 + c * 64 + jl) * 256 + s * 64);
        #pragma unroll
        for (int k = 0; k < 16; k++) {
            ulonglong2 v = wp[k];
            w2[q][2 * k]     = v.x;
            w2[q][2 * k + 1] = v.y;
        }
    }

    const int bt  = (tid >> 6) & 1;
    const int jl6 = tid & 63;
    const int jglob = c * 64 + jl6;
    float b_r = 0.f, b_z = 0.f, b_n = 0.f;
    if (tid < 128) {
        b_r = bhh[jglob];
        b_z = bhh[256 + jglob];
        b_n = bhh[512 + jglob];
    }
    for (int i = tid; i < 4 * HPAD; i += RTHREADS)
        ((float*)hb)[i] = 0.f;

    const unsigned mb0 = smem_u32(&mbar_s[0]);
    const unsigned mb1 = smem_u32(&mbar_s[1]);
    if (tid == 0) { mbar_init(mb0, 4); mbar_init(mb1, 4); }

    const float* xgb0 = xg + (size_t)b0 * T_ * G3_;
    const float* xgb1 = xg + (size_t)(b0 + 1) * T_ * G3_;
    const int xoff = (tid >> 6) * 256 + (tid & 63) + c * 64;
    float xgc0 = 0.f, xgc1 = 0.f;

    const int pidx = jglob + ((jglob >> 6) << 2);
    const unsigned addr0 = smem_u32(&hb[0][bt][pidx]);
    const unsigned addr1 = smem_u32(&hb[1][bt][pidx]);
    float hreg = 0.f;
    __syncthreads();
    cluster_barrier();

    int ph0 = 0, ph1 = 0;
    int cur = 0;

    for (int ci = 0; ci < NCH_; ci++) {
        // Gate: wait for this chunk's xg to be written.
        if (gate_arr && (gate_per_chunk || ci > 0)) {
            if (tid == 0) {
                const volatile int* p = gate_arr + (gate_per_chunk ? ci : 0);
                while (*p < gate_target) {}
                __threadfence();
            }
            __syncthreads();
        }
        const int t0c = ci * CH_;
        if (tid < 192) {                    // (re)load xg for first step of chunk
            xgc0 = xgb0[(size_t)t0c * G3_ + xoff];
            xgc1 = xgb1[(size_t)t0c * G3_ + xoff];
        }

        for (int t = t0c; t < t0c + CH_; t++) {
            if (t > 0) {
                unsigned wa = cur ? mb1 : mb0;
                int p = cur ? ph1 : ph0;
                mbar_wait_cta(wa, p);
                if (cur) ph1 ^= 1; else ph0 ^= 1;
            }
            if (tid < 192) { xgs[0][tid] = xgc0; xgs[1][tid] = xgc1; }
            float xgn0 = 0.f, xgn1 = 0.f;
            if (tid < 192 && t + 1 < T_) {  // may racily read next chunk; discarded
                xgn0 = xgb0[(size_t)(t + 1) * G3_ + xoff];
                xgn1 = xgb1[(size_t)(t + 1) * G3_ + xoff];
            }

            const ulonglong2* h2a = (const ulonglong2*)hb[cur][0];
            const ulonglong2* h2b = (const ulonglong2*)hb[cur][1];
            u64t p00 = 0, p01 = 0, p10 = 0, p11 = 0;
            u64t q00 = 0, q01 = 0, q10 = 0, q11 = 0;
            #pragma unroll
            for (int i = 0; i < 16; i++) {
                ulonglong2 ha = h2a[s * 17 + i];
                ulonglong2 hv = h2b[s * 17 + i];
                p00 = ffma2(w2[0][2 * i],     ha.x, p00);
                q00 = ffma2(w2[0][2 * i],     hv.x, q00);
                p01 = ffma2(w2[0][2 * i + 1], ha.y, p01);
                q01 = ffma2(w2[0][2 * i + 1], hv.y, q01);
                p10 = ffma2(w2[1][2 * i],     ha.x, p10);
                q10 = ffma2(w2[1][2 * i],     hv.x, q10);
                p11 = ffma2(w2[1][2 * i + 1], ha.y, p11);
                q11 = ffma2(w2[1][2 * i + 1], hv.y, q11);
            }
            float pa0 = hsum2(add2(p00, p01));
            float pa1 = hsum2(add2(p10, p11));
            float qa0 = hsum2(add2(q00, q01));
            float qa1 = hsum2(add2(q10, q11));
            pa0 += __shfl_xor_sync(0xffffffffu, pa0, 1);
            pa0 += __shfl_xor_sync(0xffffffffu, pa0, 2);
            pa1 += __shfl_xor_sync(0xffffffffu, pa1, 1);
            pa1 += __shfl_xor_sync(0xffffffffu, pa1, 2);
            qa0 += __shfl_xor_sync(0xffffffffu, qa0, 1);
            qa0 += __shfl_xor_sync(0xffffffffu, qa0, 2);
            qa1 += __shfl_xor_sync(0xffffffffu, qa1, 1);
            qa1 += __shfl_xor_sync(0xffffffffu, qa1, 2);
            if (s == 0) {
                hgc[0][rg * 2] = pa0; hgc[0][rg * 2 + 1] = pa1;
                hgc[1][rg * 2] = qa0; hgc[1][rg * 2 + 1] = qa1;
            }
            __syncthreads();

            if (tid < 128) {
                float hr = hgc[bt][jl6]       + b_r;
                float hz = hgc[bt][64 + jl6]  + b_z;
                float hn = hgc[bt][128 + jl6] + b_n;
                float xr = xgs[bt][jl6], xz = xgs[bt][64 + jl6], xn = xgs[bt][128 + jl6];
                float r  = fast_sigmoid(xr + hr);
                float z  = fast_sigmoid(xz + hz);
                float nn = fast_tanh(xn + r * hn);
                float hnew = (1.f - z) * nn + z * hreg;
                hreg = hnew;
                unsigned dsta = cur ? addr0 : addr1;
                #pragma unroll
                for (int p = 0; p < 4; p++) st_cluster_f32(dsta, p, hnew);
                out[((size_t)(b0 + bt) * T_ + t) * H_ + jglob] = hnew;
                asm volatile("bar.sync 3, 128;" ::: "memory");
                if (tid < 4) {
                    unsigned am = cur ? mb0 : mb1;
                    mbar_arrive_peer(am, (unsigned)tid);
                }
            }

            xgc0 = xgn0; xgc1 = xgn1;
            cur ^= 1;
        }

        // Signal chunk completion for downstream consumers (rec0 only).
        if (prog_arr) {
            if (tid < 128) __threadfence();   // publish this chunk's out[] stores
            __syncthreads();
            cluster_barrier();                // all 4 CTAs' stores published
            if (c == 0 && tid == 0)
                atomicAdd(prog_arr + (blockIdx.x >> 2), 1);
        }
    }
    cluster_barrier();
}

// ---------------------------------------------------------------------------
static void launch_rec(cudaStream_t st, const float* xg, const float* Whh,
                       const float* bhh, float* out,
                       const int* gate_arr, int gate_target, int gate_per_chunk,
                       int* prog_arr)
{
    cudaLaunchConfig_t cfg = {};
    cfg.gridDim  = dim3((B_ / 2) * 4, 1, 1);   // 64 CTAs = 16 clusters
    cfg.blockDim = dim3(RTHREADS, 1, 1);
    cfg.dynamicSmemBytes = 0;
    cfg.stream = st;
    cudaLaunchAttribute attrs[1];
    attrs[0].id = cudaLaunchAttributeClusterDimension;
    attrs[0].val.clusterDim.x = 4;
    attrs[0].val.clusterDim.y = 1;
    attrs[0].val.clusterDim.z = 1;
    cfg.attrs = attrs;
    cfg.numAttrs = 1;
    cudaLaunchKernelEx(&cfg, gru_rec_kernel, xg, Whh, bhh, out,
                       gate_arr, gate_target, gate_per_chunk, prog_arr);
}

extern "C" void kernel_launch(void* const* d_in, const int* in_sizes, int n_in,
                              void* d_out, int out_size)
{
    (void)in_sizes; (void)n_in; (void)out_size;
    const float* x   = (const float*)d_in[0];
    const float* Wih = (const float*)d_in[1];
    const float* Whh = (const float*)d_in[2];
    const float* bih = (const float*)d_in[3];
    const float* bhh = (const float*)d_in[4];
    float* out = (float*)d_out;

    float* xg0p; cudaGetSymbolAddress((void**)&xg0p, g_xg0);
    float* xg1p; cudaGetSymbolAddress((void**)&xg1p, g_xg1);
    float* h1p;  cudaGetSymbolAddress((void**)&h1p,  g_h1);
    int* cg0;  cudaGetSymbolAddress((void**)&cg0,  g_cnt_g0);
    int* rpr;  cudaGetSymbolAddress((void**)&rpr,  g_rec0prog);
    int* cg1;  cudaGetSymbolAddress((void**)&cg1,  g_cnt_g1);

    static cudaStream_t s1 = nullptr, s2 = nullptr;
    static cudaEvent_t evFork, evJoin, evJoin2, evG0;
    static bool infra_ok = false;
    if (!infra_ok) {
        cudaStreamCreateWithFlags(&s1, cudaStreamNonBlocking);
        cudaStreamCreateWithFlags(&s2, cudaStreamNonBlocking);
        cudaEventCreateWithFlags(&evFork, cudaEventDisableTiming);
        cudaEventCreateWithFlags(&evJoin, cudaEventDisableTiming);
        cudaEventCreateWithFlags(&evJoin2, cudaEventDisableTiming);
        cudaEventCreateWithFlags(&evG0, cudaEventDisableTiming);
        cudaFuncSetAttribute(gemm_tc_kernel,
                             cudaFuncAttributeMaxDynamicSharedMemorySize, SM_TOT);
        infra_ok = true;
    }

    // Reset progress counters (replay-safe; part of the captured graph).
    cudaMemsetAsync(cg0, 0, sizeof(int), 0);
    cudaMemsetAsync(rpr, 0, 16 * sizeof(int), 0);
    cudaMemsetAsync(cg1, 0, NCH_ * sizeof(int), 0);

    cudaEventRecord(evFork, 0);
    cudaStreamWaitEvent(s1, evFork, 0);
    cudaStreamWaitEvent(s2, evFork, 0);

    // gemm0 chunk 0 on stream 0 (rec0 needs it immediately; stream-ordered).
    {
        dim3 gc0(B_ * (CH_ / 128), G3_ / 64);
        gemm_tc_kernel<<<gc0, GT, SM_TOT, 0>>>(x, Wih, bih, xg0p, 0, CH_ / 128,
                                               nullptr, 0, nullptr);
    }
    // gemm0 remainder on s2 (5760 CTAs), signals g_cnt_g0.
    {
        int bpb = (T_ - CH_) / 128;
        dim3 gcr(B_ * bpb, G3_ / 64);
        gemm_tc_kernel<<<gcr, GT, SM_TOT, s2>>>(x, Wih, bih, xg0p, CH_, bpb,
                                                nullptr, 0, cg0);
        cudaEventRecord(evG0, s2);
    }

    // Persistent rec0 (stream 0): gated on g_cnt_g0 for ci>=1; signals rpr.
    launch_rec(0, xg0p, Whh, bhh, h1p, cg0, 5760, 0, rpr);

    // gemm1 chunk kernels on s2 (in order after gemm0_rest); each spins on
    // rec0 progress and signals g_cnt_g1[i].
    const float* Wih1 = Wih + (size_t)G3_ * D_;
    const float* Whh1 = Whh + (size_t)G3_ * H_;
    const float* bih1 = bih + G3_;
    const float* bhh1 = bhh + G3_;
    for (int i = 0; i < NCH_; i++) {
        dim3 g1(B_ * (CH_ / 128), G3_ / 64);
        gemm_tc_kernel<<<g1, GT, SM_TOT, s2>>>(h1p, Wih1, bih1, xg1p,
                                               i * CH_, CH_ / 128,
                                               rpr, i + 1, cg1 + i);
    }
    cudaEventRecord(evJoin2, s2);

    // Persistent rec1 (s1, after gemm0_rest so it gets SMs first): gated
    // per-chunk on g_cnt_g1[ci] (384 CTAs each); no progress signal.
    cudaStreamWaitEvent(s1, evG0, 0);
    launch_rec(s1, xg1p, Whh1, bhh1, out, cg1, 384, 1, nullptr);

    cudaEventRecord(evJoin, s1);
    cudaStreamWaitEvent(0, evJoin, 0);
    cudaStreamWaitEvent(0, evJoin2, 0);
}